// round 1
// baseline (speedup 1.0000x reference)
#include <cuda_runtime.h>
#include <math.h>

#define BATCH 4
#define SEQ   2048
#define DMODEL 1024
#define NH    16
#define DH    64

// Scratch (device globals: allocation-free per harness rules)
__device__ float g_Q[BATCH * NH * SEQ * DH];    // [b,h,l,d]
__device__ float g_K[BATCH * NH * SEQ * DH];
__device__ float g_V[BATCH * NH * SEQ * DH];
__device__ float g_ctx[BATCH * SEQ * DMODEL];   // [b,l,h*64+d]

// ---------------------------------------------------------------------------
// SGEMM with bias: out[M=8192, N=1024] = A[8192,1024] @ W[1024,1024] + bias
// 128x128 block tile, K-tile 8, 256 threads, 8x8 per-thread microtile.
// SPLIT_HEADS: scatter columns into [b,h,l,d] layout (for Q/K/V projections).
// ---------------------------------------------------------------------------
template <bool SPLIT_HEADS>
__global__ __launch_bounds__(256)
void gemm_bias_kernel(const float* __restrict__ A,
                      const float* __restrict__ W,
                      const float* __restrict__ bias,
                      float* __restrict__ out)
{
    __shared__ float As[8][132];   // A tile transposed [k][m], padded
    __shared__ float Bs[8][128];   // W tile [k][n]

    const int tid = threadIdx.x;
    const int bm  = blockIdx.y * 128;
    const int bn  = blockIdx.x * 128;
    const int tx  = tid & 15;      // 0..15 -> 8 output cols each
    const int ty  = tid >> 4;      // 0..15 -> 8 output rows each

    // Global load assignments
    const int arow = tid >> 1;            // 0..127
    const int ak   = (tid & 1) * 4;       // 0 or 4
    const int brow = tid >> 5;            // 0..7 (k within tile)
    const int bcol = (tid & 31) * 4;      // 0..124

    const float* Aptr = A + (size_t)(bm + arow) * 1024 + ak;
    const float* Wptr = W + (size_t)brow * 1024 + bn + bcol;

    float acc[8][8];
    #pragma unroll
    for (int i = 0; i < 8; i++)
        #pragma unroll
        for (int j = 0; j < 8; j++) acc[i][j] = 0.f;

    for (int k0 = 0; k0 < 1024; k0 += 8) {
        float4 av = *(const float4*)(Aptr + k0);
        float4 wv = *(const float4*)(Wptr + (size_t)k0 * 1024);
        __syncthreads();
        As[ak + 0][arow] = av.x;
        As[ak + 1][arow] = av.y;
        As[ak + 2][arow] = av.z;
        As[ak + 3][arow] = av.w;
        *(float4*)&Bs[brow][bcol] = wv;
        __syncthreads();

        #pragma unroll
        for (int kk = 0; kk < 8; kk++) {
            float a[8], b[8];
            *(float4*)(a + 0) = *(const float4*)&As[kk][ty * 8 + 0];
            *(float4*)(a + 4) = *(const float4*)&As[kk][ty * 8 + 4];
            *(float4*)(b + 0) = *(const float4*)&Bs[kk][tx * 8 + 0];
            *(float4*)(b + 4) = *(const float4*)&Bs[kk][tx * 8 + 4];
            #pragma unroll
            for (int i = 0; i < 8; i++)
                #pragma unroll
                for (int j = 0; j < 8; j++)
                    acc[i][j] += a[i] * b[j];
        }
    }

    // Epilogue: add bias, store (optionally head-split scatter)
    #pragma unroll
    for (int i = 0; i < 8; i++) {
        const int r = bm + ty * 8 + i;
        #pragma unroll
        for (int j4 = 0; j4 < 8; j4 += 4) {
            const int c = bn + tx * 8 + j4;
            float4 v;
            v.x = acc[i][j4 + 0] + bias[c + 0];
            v.y = acc[i][j4 + 1] + bias[c + 1];
            v.z = acc[i][j4 + 2] + bias[c + 2];
            v.w = acc[i][j4 + 3] + bias[c + 3];
            if (SPLIT_HEADS) {
                const int b_ = r >> 11;       // r / 2048
                const int l_ = r & 2047;
                const int h_ = c >> 6;        // c / 64
                const int d_ = c & 63;
                float* o = out + ((size_t)((b_ * NH + h_) * SEQ + l_)) * DH + d_;
                *(float4*)o = v;
            } else {
                *(float4*)(out + (size_t)r * 1024 + c) = v;
            }
        }
    }
}

// ---------------------------------------------------------------------------
// Flash attention (causal), fp32. One block per (q-tile of 64, b*h).
// 256 threads: 16x16 grid, 4x4 microtile over the 64x64 S / O tiles.
// ---------------------------------------------------------------------------
__global__ __launch_bounds__(256)
void attn_kernel()
{
    extern __shared__ float sm[];
    float* Qs = sm;                 // [64 d][68] transposed
    float* Ks = Qs + 64 * 68;       // [64 d][68] transposed
    float* Vs = Ks + 64 * 68;       // [64 kv][68] natural
    float* Ps = Vs + 64 * 68;       // [64 q][68]

    const int tid = threadIdx.x;
    const int tx  = tid & 15;
    const int ty  = tid >> 4;
    const int qt  = blockIdx.x;     // 0..31
    const int bh  = blockIdx.y;     // 0..63

    const float* Qg = g_Q + ((size_t)bh * SEQ + qt * 64) * DH;
    const float* Kg = g_K + (size_t)bh * SEQ * DH;
    const float* Vg = g_V + (size_t)bh * SEQ * DH;

    // Load Q tile transposed: Qs[d][q]
    for (int idx = tid; idx < 64 * 16; idx += 256) {
        const int q  = idx >> 4;
        const int d4 = (idx & 15) << 2;
        float4 v = *(const float4*)(Qg + q * 64 + d4);
        Qs[(d4 + 0) * 68 + q] = v.x;
        Qs[(d4 + 1) * 68 + q] = v.y;
        Qs[(d4 + 2) * 68 + q] = v.z;
        Qs[(d4 + 3) * 68 + q] = v.w;
    }

    float O[4][4];
    float m_prev[4], lsum[4];
    #pragma unroll
    for (int i = 0; i < 4; i++) {
        m_prev[i] = -1e30f; lsum[i] = 0.f;
        #pragma unroll
        for (int j = 0; j < 4; j++) O[i][j] = 0.f;
    }

    const float scale = 0.125f;   // 1/sqrt(64)
    const int ntiles = qt + 1;

    for (int jt = 0; jt < ntiles; jt++) {
        __syncthreads();   // Q loaded (first iter) / prev PV done
        // Load K transposed, V natural
        for (int idx = tid; idx < 64 * 16; idx += 256) {
            const int r  = idx >> 4;
            const int d4 = (idx & 15) << 2;
            float4 kv = *(const float4*)(Kg + (size_t)(jt * 64 + r) * 64 + d4);
            Ks[(d4 + 0) * 68 + r] = kv.x;
            Ks[(d4 + 1) * 68 + r] = kv.y;
            Ks[(d4 + 2) * 68 + r] = kv.z;
            Ks[(d4 + 3) * 68 + r] = kv.w;
            float4 vv = *(const float4*)(Vg + (size_t)(jt * 64 + r) * 64 + d4);
            *(float4*)&Vs[r * 68 + d4] = vv;
        }
        __syncthreads();

        // S = Q K^T (64x64x64), this thread: rows ty*4.., cols tx*4..
        float s[4][4];
        #pragma unroll
        for (int i = 0; i < 4; i++)
            #pragma unroll
            for (int j = 0; j < 4; j++) s[i][j] = 0.f;

        #pragma unroll 8
        for (int kd = 0; kd < 64; kd++) {
            float a[4], b[4];
            *(float4*)a = *(const float4*)&Qs[kd * 68 + ty * 4];
            *(float4*)b = *(const float4*)&Ks[kd * 68 + tx * 4];
            #pragma unroll
            for (int i = 0; i < 4; i++)
                #pragma unroll
                for (int j = 0; j < 4; j++)
                    s[i][j] += a[i] * b[j];
        }

        const bool diag = (jt == qt);
        #pragma unroll
        for (int i = 0; i < 4; i++)
            #pragma unroll
            for (int j = 0; j < 4; j++) {
                float v = s[i][j] * scale;
                if (diag && (tx * 4 + j) > (ty * 4 + i)) v = -1e30f;
                s[i][j] = v;
            }

        // Row max (reduce across the 16 tx lanes in this half-warp)
        float rm[4];
        #pragma unroll
        for (int i = 0; i < 4; i++) {
            float v = fmaxf(fmaxf(s[i][0], s[i][1]), fmaxf(s[i][2], s[i][3]));
            v = fmaxf(v, __shfl_xor_sync(0xffffffffu, v, 1));
            v = fmaxf(v, __shfl_xor_sync(0xffffffffu, v, 2));
            v = fmaxf(v, __shfl_xor_sync(0xffffffffu, v, 4));
            v = fmaxf(v, __shfl_xor_sync(0xffffffffu, v, 8));
            rm[i] = v;
        }

        float m_new[4], corr[4], rs[4];
        #pragma unroll
        for (int i = 0; i < 4; i++) {
            m_new[i] = fmaxf(m_prev[i], rm[i]);
            corr[i]  = __expf(m_prev[i] - m_new[i]);
            float sum = 0.f;
            #pragma unroll
            for (int j = 0; j < 4; j++) {
                float p = __expf(s[i][j] - m_new[i]);
                s[i][j] = p;
                sum += p;
            }
            sum += __shfl_xor_sync(0xffffffffu, sum, 1);
            sum += __shfl_xor_sync(0xffffffffu, sum, 2);
            sum += __shfl_xor_sync(0xffffffffu, sum, 4);
            sum += __shfl_xor_sync(0xffffffffu, sum, 8);
            rs[i] = sum;
        }
        #pragma unroll
        for (int i = 0; i < 4; i++) {
            lsum[i] = lsum[i] * corr[i] + rs[i];
            m_prev[i] = m_new[i];
            #pragma unroll
            for (int j = 0; j < 4; j++) O[i][j] *= corr[i];
        }

        // Store P tile
        #pragma unroll
        for (int i = 0; i < 4; i++) {
            float4 pv = make_float4(s[i][0], s[i][1], s[i][2], s[i][3]);
            *(float4*)&Ps[(ty * 4 + i) * 68 + tx * 4] = pv;
        }
        __syncthreads();

        // O += P @ V (64x64x64)
        #pragma unroll 4
        for (int kk4 = 0; kk4 < 64; kk4 += 4) {
            float bv[4][4];
            #pragma unroll
            for (int jj = 0; jj < 4; jj++)
                *(float4*)bv[jj] = *(const float4*)&Vs[(kk4 + jj) * 68 + tx * 4];
            #pragma unroll
            for (int i = 0; i < 4; i++) {
                float4 p = *(const float4*)&Ps[(ty * 4 + i) * 68 + kk4];
                #pragma unroll
                for (int j = 0; j < 4; j++)
                    O[i][j] += p.x * bv[0][j] + p.y * bv[1][j]
                             + p.z * bv[2][j] + p.w * bv[3][j];
            }
        }
    }

    // Epilogue: O / l, write ctx in [b, l, h*64+d] layout
    const int b_ = bh >> 4;
    const int h_ = bh & 15;
    #pragma unroll
    for (int i = 0; i < 4; i++) {
        const int q = qt * 64 + ty * 4 + i;
        const float inv = 1.f / lsum[i];
        float4 v = make_float4(O[i][0] * inv, O[i][1] * inv,
                               O[i][2] * inv, O[i][3] * inv);
        *(float4*)(g_ctx + ((size_t)(b_ * SEQ + q)) * DMODEL + h_ * 64 + tx * 4) = v;
    }
}

// ---------------------------------------------------------------------------
extern "C" void kernel_launch(void* const* d_in, const int* in_sizes, int n_in,
                              void* d_out, int out_size)
{
    const float* x  = (const float*)d_in[0];
    // d_in[1] = attn_mask (causal tril; implemented analytically)
    const float* Wq = (const float*)d_in[2];
    const float* bq = (const float*)d_in[3];
    const float* Wk = (const float*)d_in[4];
    const float* bk = (const float*)d_in[5];
    const float* Wv = (const float*)d_in[6];
    const float* bv = (const float*)d_in[7];
    const float* Wo = (const float*)d_in[8];
    const float* bo = (const float*)d_in[9];
    float* out = (float*)d_out;

    float *qp, *kp, *vp, *cp;
    cudaGetSymbolAddress((void**)&qp, g_Q);
    cudaGetSymbolAddress((void**)&kp, g_K);
    cudaGetSymbolAddress((void**)&vp, g_V);
    cudaGetSymbolAddress((void**)&cp, g_ctx);

    const dim3 ggrid(8, 64);   // N/128, M/128
    gemm_bias_kernel<true><<<ggrid, 256>>>(x, Wq, bq, qp);
    gemm_bias_kernel<true><<<ggrid, 256>>>(x, Wk, bk, kp);
    gemm_bias_kernel<true><<<ggrid, 256>>>(x, Wv, bv, vp);

    const int smem = 4 * 64 * 68 * (int)sizeof(float);   // 69632 B
    cudaFuncSetAttribute(attn_kernel, cudaFuncAttributeMaxDynamicSharedMemorySize, smem);
    attn_kernel<<<dim3(32, 64), 256, smem>>>();

    gemm_bias_kernel<false><<<ggrid, 256>>>(cp, Wo, bo, out);
}

// round 2
// speedup vs baseline: 1.7014x; 1.7014x over previous
#include <cuda_runtime.h>
#include <math.h>

#define BATCH 4
#define SEQ   2048
#define DMODEL 1024
#define NH    16
#define DH    64

// Scratch (device globals: allocation-free per harness rules)
__device__ float g_Q[BATCH * NH * SEQ * DH];    // [b,h,l,d]
__device__ float g_K[BATCH * NH * SEQ * DH];
__device__ float g_V[BATCH * NH * SEQ * DH];
__device__ float g_ctx[BATCH * SEQ * DMODEL];   // [b,l,h*64+d]

// ---------------------------------------------------------------------------
// tf32 helpers
// ---------------------------------------------------------------------------
__device__ __forceinline__ unsigned f2tf(float f) {
    unsigned u;
    asm("cvt.rna.tf32.f32 %0, %1;" : "=r"(u) : "f"(f));
    return u;
}

__device__ __forceinline__ void mma_tf32(float* c,
    unsigned a0, unsigned a1, unsigned a2, unsigned a3,
    unsigned b0, unsigned b1)
{
    asm("mma.sync.aligned.m16n8k8.row.col.f32.tf32.tf32.f32 "
        "{%0,%1,%2,%3}, {%4,%5,%6,%7}, {%8,%9}, {%0,%1,%2,%3};"
        : "+f"(c[0]), "+f"(c[1]), "+f"(c[2]), "+f"(c[3])
        : "r"(a0), "r"(a1), "r"(a2), "r"(a3), "r"(b0), "r"(b1));
}

// ---------------------------------------------------------------------------
// tf32 tensor-core GEMM with bias:
//   out[M=8192, N=1024] = A[8192,1024] @ W[1024,1024] + bias
// 128x128 block tile, K-tile 32, 256 threads (8 warps, 2x4),
// each warp: 64x32 via 4x4 m16n8k8 fragments.
// SPLIT_HEADS: scatter columns into [b,h,l,d] layout (Q/K/V projections).
// ---------------------------------------------------------------------------
#define APAD 36     // conflict-free A fragment loads: bank = 4*g + l4
#define BPAD 136    // conflict-free B fragment loads: bank = 8*l4 + g

template <bool SPLIT_HEADS>
__global__ __launch_bounds__(256)
void gemm_tf32_kernel(const float* __restrict__ A,
                      const float* __restrict__ W,
                      const float* __restrict__ bias,
                      float* __restrict__ out)
{
    __shared__ unsigned As[128 * APAD];   // [row][k] tf32 bits
    __shared__ unsigned Bs[32 * BPAD];    // [k][n]   tf32 bits

    const int tid    = threadIdx.x;
    const int lane   = tid & 31;
    const int wid    = tid >> 5;
    const int warp_m = wid >> 2;          // 0..1  (64 rows each)
    const int warp_n = wid & 3;           // 0..3  (32 cols each)
    const int bm     = blockIdx.y * 128;
    const int bn     = blockIdx.x * 128;
    const int g      = lane >> 2;         // 0..7
    const int l4     = lane & 3;          // 0..3

    float acc[4][4][4];
    #pragma unroll
    for (int mt = 0; mt < 4; mt++)
        #pragma unroll
        for (int nt = 0; nt < 4; nt++)
            #pragma unroll
            for (int i = 0; i < 4; i++) acc[mt][nt][i] = 0.f;

    for (int k0 = 0; k0 < 1024; k0 += 32) {
        // Global loads for this K-tile (issued before sync for overlap)
        float4 a4[4], b4[4];
        #pragma unroll
        for (int i = 0; i < 4; i++) {
            const int p  = tid + i * 256;
            const int r  = p >> 3, kc = (p & 7) << 2;
            a4[i] = *(const float4*)(A + (size_t)(bm + r) * 1024 + k0 + kc);
            const int kr = p >> 5, nc = (p & 31) << 2;
            b4[i] = *(const float4*)(W + (size_t)(k0 + kr) * 1024 + bn + nc);
        }
        __syncthreads();
        #pragma unroll
        for (int i = 0; i < 4; i++) {
            const int p  = tid + i * 256;
            const int r  = p >> 3, kc = (p & 7) << 2;
            unsigned* da = &As[r * APAD + kc];
            da[0] = f2tf(a4[i].x); da[1] = f2tf(a4[i].y);
            da[2] = f2tf(a4[i].z); da[3] = f2tf(a4[i].w);
            const int kr = p >> 5, nc = (p & 31) << 2;
            unsigned* db = &Bs[kr * BPAD + nc];
            db[0] = f2tf(b4[i].x); db[1] = f2tf(b4[i].y);
            db[2] = f2tf(b4[i].z); db[3] = f2tf(b4[i].w);
        }
        __syncthreads();

        #pragma unroll
        for (int ks = 0; ks < 4; ks++) {
            unsigned af[4][4], bf[4][2];
            #pragma unroll
            for (int mt = 0; mt < 4; mt++) {
                const int row = warp_m * 64 + mt * 16;
                af[mt][0] = As[(row + g)     * APAD + ks * 8 + l4];
                af[mt][1] = As[(row + 8 + g) * APAD + ks * 8 + l4];
                af[mt][2] = As[(row + g)     * APAD + ks * 8 + l4 + 4];
                af[mt][3] = As[(row + 8 + g) * APAD + ks * 8 + l4 + 4];
            }
            #pragma unroll
            for (int nt = 0; nt < 4; nt++) {
                const int col = warp_n * 32 + nt * 8 + g;
                bf[nt][0] = Bs[(ks * 8 + l4)     * BPAD + col];
                bf[nt][1] = Bs[(ks * 8 + 4 + l4) * BPAD + col];
            }
            #pragma unroll
            for (int mt = 0; mt < 4; mt++)
                #pragma unroll
                for (int nt = 0; nt < 4; nt++)
                    mma_tf32(acc[mt][nt],
                             af[mt][0], af[mt][1], af[mt][2], af[mt][3],
                             bf[nt][0], bf[nt][1]);
        }
    }

    // Epilogue: bias + store (optionally head-split scatter)
    #pragma unroll
    for (int mt = 0; mt < 4; mt++) {
        const int r0 = bm + warp_m * 64 + mt * 16 + g;
        const int r1 = r0 + 8;
        #pragma unroll
        for (int nt = 0; nt < 4; nt++) {
            const int c = bn + warp_n * 32 + nt * 8 + 2 * l4;
            const float bx = bias[c], by = bias[c + 1];
            float2 v0 = make_float2(acc[mt][nt][0] + bx, acc[mt][nt][1] + by);
            float2 v1 = make_float2(acc[mt][nt][2] + bx, acc[mt][nt][3] + by);
            if (SPLIT_HEADS) {
                const int h  = c >> 6, d = c & 63;
                const int b0_ = r0 >> 11, l0_ = r0 & 2047;
                const int b1_ = r1 >> 11, l1_ = r1 & 2047;
                *(float2*)(out + ((size_t)((b0_ * NH + h) * SEQ + l0_)) * DH + d) = v0;
                *(float2*)(out + ((size_t)((b1_ * NH + h) * SEQ + l1_)) * DH + d) = v1;
            } else {
                *(float2*)(out + (size_t)r0 * 1024 + c) = v0;
                *(float2*)(out + (size_t)r1 * 1024 + c) = v1;
            }
        }
    }
}

// ---------------------------------------------------------------------------
// Flash attention (causal), fp32. One block per (q-tile of 64, b*h).
// 256 threads: 16x16 grid, 4x4 microtile over the 64x64 S / O tiles.
// ---------------------------------------------------------------------------
__global__ __launch_bounds__(256)
void attn_kernel()
{
    extern __shared__ float sm[];
    float* Qs = sm;                 // [64 d][68] transposed
    float* Ks = Qs + 64 * 68;       // [64 d][68] transposed
    float* Vs = Ks + 64 * 68;       // [64 kv][68] natural
    float* Ps = Vs + 64 * 68;       // [64 q][68]

    const int tid = threadIdx.x;
    const int tx  = tid & 15;
    const int ty  = tid >> 4;
    const int qt  = blockIdx.x;     // 0..31
    const int bh  = blockIdx.y;     // 0..63

    const float* Qg = g_Q + ((size_t)bh * SEQ + qt * 64) * DH;
    const float* Kg = g_K + (size_t)bh * SEQ * DH;
    const float* Vg = g_V + (size_t)bh * SEQ * DH;

    // Load Q tile transposed: Qs[d][q]
    for (int idx = tid; idx < 64 * 16; idx += 256) {
        const int q  = idx >> 4;
        const int d4 = (idx & 15) << 2;
        float4 v = *(const float4*)(Qg + q * 64 + d4);
        Qs[(d4 + 0) * 68 + q] = v.x;
        Qs[(d4 + 1) * 68 + q] = v.y;
        Qs[(d4 + 2) * 68 + q] = v.z;
        Qs[(d4 + 3) * 68 + q] = v.w;
    }

    float O[4][4];
    float m_prev[4], lsum[4];
    #pragma unroll
    for (int i = 0; i < 4; i++) {
        m_prev[i] = -1e30f; lsum[i] = 0.f;
        #pragma unroll
        for (int j = 0; j < 4; j++) O[i][j] = 0.f;
    }

    const float scale = 0.125f;   // 1/sqrt(64)
    const int ntiles = qt + 1;

    for (int jt = 0; jt < ntiles; jt++) {
        __syncthreads();   // Q loaded (first iter) / prev PV done
        // Load K transposed, V natural
        for (int idx = tid; idx < 64 * 16; idx += 256) {
            const int r  = idx >> 4;
            const int d4 = (idx & 15) << 2;
            float4 kv = *(const float4*)(Kg + (size_t)(jt * 64 + r) * 64 + d4);
            Ks[(d4 + 0) * 68 + r] = kv.x;
            Ks[(d4 + 1) * 68 + r] = kv.y;
            Ks[(d4 + 2) * 68 + r] = kv.z;
            Ks[(d4 + 3) * 68 + r] = kv.w;
            float4 vv = *(const float4*)(Vg + (size_t)(jt * 64 + r) * 64 + d4);
            *(float4*)&Vs[r * 68 + d4] = vv;
        }
        __syncthreads();

        // S = Q K^T (64x64x64)
        float s[4][4];
        #pragma unroll
        for (int i = 0; i < 4; i++)
            #pragma unroll
            for (int j = 0; j < 4; j++) s[i][j] = 0.f;

        #pragma unroll 8
        for (int kd = 0; kd < 64; kd++) {
            float a[4], b[4];
            *(float4*)a = *(const float4*)&Qs[kd * 68 + ty * 4];
            *(float4*)b = *(const float4*)&Ks[kd * 68 + tx * 4];
            #pragma unroll
            for (int i = 0; i < 4; i++)
                #pragma unroll
                for (int j = 0; j < 4; j++)
                    s[i][j] += a[i] * b[j];
        }

        const bool diag = (jt == qt);
        #pragma unroll
        for (int i = 0; i < 4; i++)
            #pragma unroll
            for (int j = 0; j < 4; j++) {
                float v = s[i][j] * scale;
                if (diag && (tx * 4 + j) > (ty * 4 + i)) v = -1e30f;
                s[i][j] = v;
            }

        // Row max
        float rm[4];
        #pragma unroll
        for (int i = 0; i < 4; i++) {
            float v = fmaxf(fmaxf(s[i][0], s[i][1]), fmaxf(s[i][2], s[i][3]));
            v = fmaxf(v, __shfl_xor_sync(0xffffffffu, v, 1));
            v = fmaxf(v, __shfl_xor_sync(0xffffffffu, v, 2));
            v = fmaxf(v, __shfl_xor_sync(0xffffffffu, v, 4));
            v = fmaxf(v, __shfl_xor_sync(0xffffffffu, v, 8));
            rm[i] = v;
        }

        float m_new[4], corr[4], rs[4];
        #pragma unroll
        for (int i = 0; i < 4; i++) {
            m_new[i] = fmaxf(m_prev[i], rm[i]);
            corr[i]  = __expf(m_prev[i] - m_new[i]);
            float sum = 0.f;
            #pragma unroll
            for (int j = 0; j < 4; j++) {
                float p = __expf(s[i][j] - m_new[i]);
                s[i][j] = p;
                sum += p;
            }
            sum += __shfl_xor_sync(0xffffffffu, sum, 1);
            sum += __shfl_xor_sync(0xffffffffu, sum, 2);
            sum += __shfl_xor_sync(0xffffffffu, sum, 4);
            sum += __shfl_xor_sync(0xffffffffu, sum, 8);
            rs[i] = sum;
        }
        #pragma unroll
        for (int i = 0; i < 4; i++) {
            lsum[i] = lsum[i] * corr[i] + rs[i];
            m_prev[i] = m_new[i];
            #pragma unroll
            for (int j = 0; j < 4; j++) O[i][j] *= corr[i];
        }

        // Store P tile
        #pragma unroll
        for (int i = 0; i < 4; i++) {
            float4 pv = make_float4(s[i][0], s[i][1], s[i][2], s[i][3]);
            *(float4*)&Ps[(ty * 4 + i) * 68 + tx * 4] = pv;
        }
        __syncthreads();

        // O += P @ V (64x64x64)
        #pragma unroll 4
        for (int kk4 = 0; kk4 < 64; kk4 += 4) {
            float bv[4][4];
            #pragma unroll
            for (int jj = 0; jj < 4; jj++)
                *(float4*)bv[jj] = *(const float4*)&Vs[(kk4 + jj) * 68 + tx * 4];
            #pragma unroll
            for (int i = 0; i < 4; i++) {
                float4 p = *(const float4*)&Ps[(ty * 4 + i) * 68 + kk4];
                #pragma unroll
                for (int j = 0; j < 4; j++)
                    O[i][j] += p.x * bv[0][j] + p.y * bv[1][j]
                             + p.z * bv[2][j] + p.w * bv[3][j];
            }
        }
    }

    // Epilogue: O / l, write ctx in [b, l, h*64+d] layout
    const int b_ = bh >> 4;
    const int h_ = bh & 15;
    #pragma unroll
    for (int i = 0; i < 4; i++) {
        const int q = qt * 64 + ty * 4 + i;
        const float inv = 1.f / lsum[i];
        float4 v = make_float4(O[i][0] * inv, O[i][1] * inv,
                               O[i][2] * inv, O[i][3] * inv);
        *(float4*)(g_ctx + ((size_t)(b_ * SEQ + q)) * DMODEL + h_ * 64 + tx * 4) = v;
    }
}

// ---------------------------------------------------------------------------
extern "C" void kernel_launch(void* const* d_in, const int* in_sizes, int n_in,
                              void* d_out, int out_size)
{
    const float* x  = (const float*)d_in[0];
    // d_in[1] = attn_mask (causal tril; implemented analytically)
    const float* Wq = (const float*)d_in[2];
    const float* bq = (const float*)d_in[3];
    const float* Wk = (const float*)d_in[4];
    const float* bk = (const float*)d_in[5];
    const float* Wv = (const float*)d_in[6];
    const float* bv = (const float*)d_in[7];
    const float* Wo = (const float*)d_in[8];
    const float* bo = (const float*)d_in[9];
    float* out = (float*)d_out;

    float *qp, *kp, *vp, *cp;
    cudaGetSymbolAddress((void**)&qp, g_Q);
    cudaGetSymbolAddress((void**)&kp, g_K);
    cudaGetSymbolAddress((void**)&vp, g_V);
    cudaGetSymbolAddress((void**)&cp, g_ctx);

    const dim3 ggrid(8, 64);   // N/128, M/128
    gemm_tf32_kernel<true><<<ggrid, 256>>>(x, Wq, bq, qp);
    gemm_tf32_kernel<true><<<ggrid, 256>>>(x, Wk, bk, kp);
    gemm_tf32_kernel<true><<<ggrid, 256>>>(x, Wv, bv, vp);

    const int smem = 4 * 64 * 68 * (int)sizeof(float);   // 69632 B
    cudaFuncSetAttribute(attn_kernel, cudaFuncAttributeMaxDynamicSharedMemorySize, smem);
    attn_kernel<<<dim3(32, 64), 256, smem>>>();

    gemm_tf32_kernel<false><<<ggrid, 256>>>(cp, Wo, bo, out);
}

// round 3
// speedup vs baseline: 2.9052x; 1.7075x over previous
#include <cuda_runtime.h>
#include <math.h>

#define BATCH 4
#define SEQ   2048
#define DMODEL 1024
#define NH    16
#define DH    64

// Scratch (device globals: allocation-free per harness rules)
__device__ float g_Q[BATCH * NH * SEQ * DH];    // [b,h,l,d]
__device__ float g_K[BATCH * NH * SEQ * DH];
__device__ float g_V[BATCH * NH * SEQ * DH];
__device__ float g_ctx[BATCH * SEQ * DMODEL];   // [b,l,h*64+d]

// ---------------------------------------------------------------------------
// tf32 helpers
// ---------------------------------------------------------------------------
__device__ __forceinline__ unsigned f2tf(float f) {
    unsigned u;
    asm("cvt.rna.tf32.f32 %0, %1;" : "=r"(u) : "f"(f));
    return u;
}

__device__ __forceinline__ void mma_tf32(float* c,
    unsigned a0, unsigned a1, unsigned a2, unsigned a3,
    unsigned b0, unsigned b1)
{
    asm("mma.sync.aligned.m16n8k8.row.col.f32.tf32.tf32.f32 "
        "{%0,%1,%2,%3}, {%4,%5,%6,%7}, {%8,%9}, {%0,%1,%2,%3};"
        : "+f"(c[0]), "+f"(c[1]), "+f"(c[2]), "+f"(c[3])
        : "r"(a0), "r"(a1), "r"(a2), "r"(a3), "r"(b0), "r"(b1));
}

// ---------------------------------------------------------------------------
// tf32 tensor-core GEMM with bias:
//   out[M=8192, N=1024] = A[8192,1024] @ W[1024,1024] + bias
// 128x128 block tile, K-tile 32, 256 threads (8 warps, 2x4),
// each warp: 64x32 via 4x4 m16n8k8 fragments.
// ---------------------------------------------------------------------------
#define APAD 36     // conflict-free A fragment loads
#define BPAD 136    // conflict-free B fragment loads

template <bool SPLIT_HEADS>
__global__ __launch_bounds__(256)
void gemm_tf32_kernel(const float* __restrict__ A,
                      const float* __restrict__ W,
                      const float* __restrict__ bias,
                      float* __restrict__ out)
{
    __shared__ unsigned As[128 * APAD];   // [row][k] tf32 bits
    __shared__ unsigned Bs[32 * BPAD];    // [k][n]   tf32 bits

    const int tid    = threadIdx.x;
    const int lane   = tid & 31;
    const int wid    = tid >> 5;
    const int warp_m = wid >> 2;
    const int warp_n = wid & 3;
    const int bm     = blockIdx.y * 128;
    const int bn     = blockIdx.x * 128;
    const int g      = lane >> 2;
    const int l4     = lane & 3;

    float acc[4][4][4];
    #pragma unroll
    for (int mt = 0; mt < 4; mt++)
        #pragma unroll
        for (int nt = 0; nt < 4; nt++)
            #pragma unroll
            for (int i = 0; i < 4; i++) acc[mt][nt][i] = 0.f;

    for (int k0 = 0; k0 < 1024; k0 += 32) {
        float4 a4[4], b4[4];
        #pragma unroll
        for (int i = 0; i < 4; i++) {
            const int p  = tid + i * 256;
            const int r  = p >> 3, kc = (p & 7) << 2;
            a4[i] = *(const float4*)(A + (size_t)(bm + r) * 1024 + k0 + kc);
            const int kr = p >> 5, nc = (p & 31) << 2;
            b4[i] = *(const float4*)(W + (size_t)(k0 + kr) * 1024 + bn + nc);
        }
        __syncthreads();
        #pragma unroll
        for (int i = 0; i < 4; i++) {
            const int p  = tid + i * 256;
            const int r  = p >> 3, kc = (p & 7) << 2;
            unsigned* da = &As[r * APAD + kc];
            da[0] = f2tf(a4[i].x); da[1] = f2tf(a4[i].y);
            da[2] = f2tf(a4[i].z); da[3] = f2tf(a4[i].w);
            const int kr = p >> 5, nc = (p & 31) << 2;
            unsigned* db = &Bs[kr * BPAD + nc];
            db[0] = f2tf(b4[i].x); db[1] = f2tf(b4[i].y);
            db[2] = f2tf(b4[i].z); db[3] = f2tf(b4[i].w);
        }
        __syncthreads();

        #pragma unroll
        for (int ks = 0; ks < 4; ks++) {
            unsigned af[4][4], bf[4][2];
            #pragma unroll
            for (int mt = 0; mt < 4; mt++) {
                const int row = warp_m * 64 + mt * 16;
                af[mt][0] = As[(row + g)     * APAD + ks * 8 + l4];
                af[mt][1] = As[(row + 8 + g) * APAD + ks * 8 + l4];
                af[mt][2] = As[(row + g)     * APAD + ks * 8 + l4 + 4];
                af[mt][3] = As[(row + 8 + g) * APAD + ks * 8 + l4 + 4];
            }
            #pragma unroll
            for (int nt = 0; nt < 4; nt++) {
                const int col = warp_n * 32 + nt * 8 + g;
                bf[nt][0] = Bs[(ks * 8 + l4)     * BPAD + col];
                bf[nt][1] = Bs[(ks * 8 + 4 + l4) * BPAD + col];
            }
            #pragma unroll
            for (int mt = 0; mt < 4; mt++)
                #pragma unroll
                for (int nt = 0; nt < 4; nt++)
                    mma_tf32(acc[mt][nt],
                             af[mt][0], af[mt][1], af[mt][2], af[mt][3],
                             bf[nt][0], bf[nt][1]);
        }
    }

    #pragma unroll
    for (int mt = 0; mt < 4; mt++) {
        const int r0 = bm + warp_m * 64 + mt * 16 + g;
        const int r1 = r0 + 8;
        #pragma unroll
        for (int nt = 0; nt < 4; nt++) {
            const int c = bn + warp_n * 32 + nt * 8 + 2 * l4;
            const float bx = bias[c], by = bias[c + 1];
            float2 v0 = make_float2(acc[mt][nt][0] + bx, acc[mt][nt][1] + by);
            float2 v1 = make_float2(acc[mt][nt][2] + bx, acc[mt][nt][3] + by);
            if (SPLIT_HEADS) {
                const int h  = c >> 6, d = c & 63;
                const int b0_ = r0 >> 11, l0_ = r0 & 2047;
                const int b1_ = r1 >> 11, l1_ = r1 & 2047;
                *(float2*)(out + ((size_t)((b0_ * NH + h) * SEQ + l0_)) * DH + d) = v0;
                *(float2*)(out + ((size_t)((b1_ * NH + h) * SEQ + l1_)) * DH + d) = v1;
            } else {
                *(float2*)(out + (size_t)r0 * 1024 + c) = v0;
                *(float2*)(out + (size_t)r1 * 1024 + c) = v1;
            }
        }
    }
}

// ---------------------------------------------------------------------------
// Flash attention (causal) on tensor cores (tf32 mma.m16n8k8).
// Block = 128 threads (4 warps); q-tile 64 (16 rows/warp); kv tiles of 64.
// Softmax scale folded into Q at load. Online softmax on mma C-fragments
// (row spread over a lane-quad -> shfl_xor 1,2 reductions only).
// ---------------------------------------------------------------------------
#define PAD 68

__global__ __launch_bounds__(128)
void attn_mma_kernel()
{
    extern __shared__ unsigned smu[];
    unsigned* Qs = smu;               // [64][PAD] tf32 (pre-scaled)
    unsigned* Ks = Qs + 64 * PAD;     // [kv][d]
    unsigned* Vs = Ks + 64 * PAD;     // [kv][d]
    unsigned* Ps = Vs + 64 * PAD;     // [q][kv] tf32 (per-warp rows)

    const int tid  = threadIdx.x;
    const int lane = tid & 31;
    const int wid  = tid >> 5;        // 0..3
    const int g    = lane >> 2;       // 0..7
    const int l4   = lane & 3;        // 0..3
    const int qt   = blockIdx.x;      // 0..31
    const int bh   = blockIdx.y;      // 0..63
    const int m0   = wid * 16;        // warp's q-row base within tile

    const float* Qg = g_Q + ((size_t)bh * SEQ + qt * 64) * DH;
    const float* Kg = g_K + (size_t)bh * SEQ * DH;
    const float* Vg = g_V + (size_t)bh * SEQ * DH;

    // Load Q tile (pre-scaled by 1/sqrt(dh)=0.125), converted to tf32
    for (int i = tid; i < 64 * 16; i += 128) {
        const int q = i >> 4, d4 = (i & 15) << 2;
        float4 v = *(const float4*)(Qg + q * 64 + d4);
        unsigned* dq = &Qs[q * PAD + d4];
        dq[0] = f2tf(v.x * 0.125f); dq[1] = f2tf(v.y * 0.125f);
        dq[2] = f2tf(v.z * 0.125f); dq[3] = f2tf(v.w * 0.125f);
    }
    __syncthreads();

    // Preload Q A-fragments (8 k-steps over d=64)
    unsigned qa[8][4];
    #pragma unroll
    for (int ks = 0; ks < 8; ks++) {
        qa[ks][0] = Qs[(m0 + g)     * PAD + ks * 8 + l4];
        qa[ks][1] = Qs[(m0 + 8 + g) * PAD + ks * 8 + l4];
        qa[ks][2] = Qs[(m0 + g)     * PAD + ks * 8 + l4 + 4];
        qa[ks][3] = Qs[(m0 + 8 + g) * PAD + ks * 8 + l4 + 4];
    }

    float o[8][4];
    #pragma unroll
    for (int nt = 0; nt < 8; nt++)
        #pragma unroll
        for (int i = 0; i < 4; i++) o[nt][i] = 0.f;
    float mrow[2] = {-1e30f, -1e30f};
    float lrow[2] = {0.f, 0.f};

    const int r0g = qt * 64 + m0 + g;      // global q row (lo)
    const int r1g = r0g + 8;               // global q row (hi)
    const int ntiles = qt + 1;

    for (int jt = 0; jt < ntiles; jt++) {
        __syncthreads();   // prev iter's K/V reads done
        for (int i = tid; i < 64 * 16; i += 128) {
            const int r = i >> 4, d4 = (i & 15) << 2;
            float4 kv = *(const float4*)(Kg + (size_t)(jt * 64 + r) * 64 + d4);
            unsigned* dk = &Ks[r * PAD + d4];
            dk[0] = f2tf(kv.x); dk[1] = f2tf(kv.y);
            dk[2] = f2tf(kv.z); dk[3] = f2tf(kv.w);
            float4 vv = *(const float4*)(Vg + (size_t)(jt * 64 + r) * 64 + d4);
            unsigned* dv = &Vs[r * PAD + d4];
            dv[0] = f2tf(vv.x); dv[1] = f2tf(vv.y);
            dv[2] = f2tf(vv.z); dv[3] = f2tf(vv.w);
        }
        __syncthreads();

        // S = Q K^T : per warp 16x64, accum fragments s[8 n-tiles][4]
        float s[8][4];
        #pragma unroll
        for (int nt = 0; nt < 8; nt++)
            #pragma unroll
            for (int i = 0; i < 4; i++) s[nt][i] = 0.f;

        #pragma unroll
        for (int nt = 0; nt < 8; nt++) {
            const unsigned* krow = &Ks[(nt * 8 + g) * PAD];
            #pragma unroll
            for (int ks = 0; ks < 8; ks++) {
                const unsigned b0 = krow[ks * 8 + l4];
                const unsigned b1 = krow[ks * 8 + l4 + 4];
                mma_tf32(s[nt], qa[ks][0], qa[ks][1], qa[ks][2], qa[ks][3], b0, b1);
            }
        }

        // Causal mask (diagonal tile only)
        if (jt == qt) {
            #pragma unroll
            for (int nt = 0; nt < 8; nt++) {
                const int c = jt * 64 + nt * 8 + 2 * l4;
                if (c     > r0g) s[nt][0] = -1e30f;
                if (c + 1 > r0g) s[nt][1] = -1e30f;
                if (c     > r1g) s[nt][2] = -1e30f;
                if (c + 1 > r1g) s[nt][3] = -1e30f;
            }
        }

        // Row max over 16 vals/thread + quad shfl
        float mx0 = -1e30f, mx1 = -1e30f;
        #pragma unroll
        for (int nt = 0; nt < 8; nt++) {
            mx0 = fmaxf(mx0, fmaxf(s[nt][0], s[nt][1]));
            mx1 = fmaxf(mx1, fmaxf(s[nt][2], s[nt][3]));
        }
        mx0 = fmaxf(mx0, __shfl_xor_sync(0xffffffffu, mx0, 1));
        mx0 = fmaxf(mx0, __shfl_xor_sync(0xffffffffu, mx0, 2));
        mx1 = fmaxf(mx1, __shfl_xor_sync(0xffffffffu, mx1, 1));
        mx1 = fmaxf(mx1, __shfl_xor_sync(0xffffffffu, mx1, 2));

        const float mn0 = fmaxf(mrow[0], mx0);
        const float mn1 = fmaxf(mrow[1], mx1);
        const float c0 = __expf(mrow[0] - mn0);
        const float c1 = __expf(mrow[1] - mn1);

        float sum0 = 0.f, sum1 = 0.f;
        #pragma unroll
        for (int nt = 0; nt < 8; nt++) {
            s[nt][0] = __expf(s[nt][0] - mn0);
            s[nt][1] = __expf(s[nt][1] - mn0);
            s[nt][2] = __expf(s[nt][2] - mn1);
            s[nt][3] = __expf(s[nt][3] - mn1);
            sum0 += s[nt][0] + s[nt][1];
            sum1 += s[nt][2] + s[nt][3];
        }
        sum0 += __shfl_xor_sync(0xffffffffu, sum0, 1);
        sum0 += __shfl_xor_sync(0xffffffffu, sum0, 2);
        sum1 += __shfl_xor_sync(0xffffffffu, sum1, 1);
        sum1 += __shfl_xor_sync(0xffffffffu, sum1, 2);

        lrow[0] = lrow[0] * c0 + sum0;
        lrow[1] = lrow[1] * c1 + sum1;
        mrow[0] = mn0;
        mrow[1] = mn1;
        #pragma unroll
        for (int nt = 0; nt < 8; nt++) {
            o[nt][0] *= c0; o[nt][1] *= c0;
            o[nt][2] *= c1; o[nt][3] *= c1;
        }

        // Store P as tf32 to this warp's rows of Ps (no cross-warp dep)
        #pragma unroll
        for (int nt = 0; nt < 8; nt++) {
            uint2 p0 = make_uint2(f2tf(s[nt][0]), f2tf(s[nt][1]));
            uint2 p1 = make_uint2(f2tf(s[nt][2]), f2tf(s[nt][3]));
            *(uint2*)&Ps[(m0 + g)     * PAD + nt * 8 + 2 * l4] = p0;
            *(uint2*)&Ps[(m0 + 8 + g) * PAD + nt * 8 + 2 * l4] = p1;
        }
        __syncwarp();

        // O += P @ V : per warp 16x64, K(kv)=64 in 8 steps
        #pragma unroll
        for (int ks = 0; ks < 8; ks++) {
            const unsigned pa0 = Ps[(m0 + g)     * PAD + ks * 8 + l4];
            const unsigned pa1 = Ps[(m0 + 8 + g) * PAD + ks * 8 + l4];
            const unsigned pa2 = Ps[(m0 + g)     * PAD + ks * 8 + l4 + 4];
            const unsigned pa3 = Ps[(m0 + 8 + g) * PAD + ks * 8 + l4 + 4];
            const unsigned* v0 = &Vs[(ks * 8 + l4)     * PAD];
            const unsigned* v1 = &Vs[(ks * 8 + l4 + 4) * PAD];
            #pragma unroll
            for (int nt = 0; nt < 8; nt++)
                mma_tf32(o[nt], pa0, pa1, pa2, pa3, v0[nt * 8 + g], v1[nt * 8 + g]);
        }
    }

    // Epilogue: normalize, write ctx [b, l, h*64+d]
    const int b_ = bh >> 4;
    const int h_ = bh & 15;
    const float inv0 = 1.f / lrow[0];
    const float inv1 = 1.f / lrow[1];
    float* c0p = g_ctx + ((size_t)(b_ * SEQ + qt * 64 + m0 + g))     * DMODEL + h_ * 64;
    float* c1p = g_ctx + ((size_t)(b_ * SEQ + qt * 64 + m0 + 8 + g)) * DMODEL + h_ * 64;
    #pragma unroll
    for (int nt = 0; nt < 8; nt++) {
        *(float2*)(c0p + nt * 8 + 2 * l4) = make_float2(o[nt][0] * inv0, o[nt][1] * inv0);
        *(float2*)(c1p + nt * 8 + 2 * l4) = make_float2(o[nt][2] * inv1, o[nt][3] * inv1);
    }
}

// ---------------------------------------------------------------------------
extern "C" void kernel_launch(void* const* d_in, const int* in_sizes, int n_in,
                              void* d_out, int out_size)
{
    const float* x  = (const float*)d_in[0];
    const float* Wq = (const float*)d_in[2];
    const float* bq = (const float*)d_in[3];
    const float* Wk = (const float*)d_in[4];
    const float* bk = (const float*)d_in[5];
    const float* Wv = (const float*)d_in[6];
    const float* bv = (const float*)d_in[7];
    const float* Wo = (const float*)d_in[8];
    const float* bo = (const float*)d_in[9];
    float* out = (float*)d_out;

    float *qp, *kp, *vp, *cp;
    cudaGetSymbolAddress((void**)&qp, g_Q);
    cudaGetSymbolAddress((void**)&kp, g_K);
    cudaGetSymbolAddress((void**)&vp, g_V);
    cudaGetSymbolAddress((void**)&cp, g_ctx);

    const dim3 ggrid(8, 64);   // N/128, M/128
    gemm_tf32_kernel<true><<<ggrid, 256>>>(x, Wq, bq, qp);
    gemm_tf32_kernel<true><<<ggrid, 256>>>(x, Wk, bk, kp);
    gemm_tf32_kernel<true><<<ggrid, 256>>>(x, Wv, bv, vp);

    const int smem = 4 * 64 * PAD * (int)sizeof(unsigned);   // 69632 B
    cudaFuncSetAttribute(attn_mma_kernel, cudaFuncAttributeMaxDynamicSharedMemorySize, smem);
    attn_mma_kernel<<<dim3(32, 64), 128, smem>>>();

    gemm_tf32_kernel<false><<<ggrid, 256>>>(cp, Wo, bo, out);
}

// round 4
// speedup vs baseline: 3.1522x; 1.0850x over previous
#include <cuda_runtime.h>
#include <math.h>

#define BATCH 4
#define SEQ   2048
#define DMODEL 1024
#define NH    16
#define DH    64

// Scratch (device globals: allocation-free per harness rules)
__device__ float g_Q[BATCH * NH * SEQ * DH];    // [b,h,l,d]
__device__ float g_K[BATCH * NH * SEQ * DH];
__device__ float g_V[BATCH * NH * SEQ * DH];
__device__ float g_ctx[BATCH * SEQ * DMODEL];   // [b,l,h*64+d]

// ---------------------------------------------------------------------------
// tf32 helpers
// ---------------------------------------------------------------------------
__device__ __forceinline__ unsigned f2tf(float f) {
    unsigned u;
    asm("cvt.rna.tf32.f32 %0, %1;" : "=r"(u) : "f"(f));
    return u;
}

__device__ __forceinline__ void mma_tf32(float* c,
    unsigned a0, unsigned a1, unsigned a2, unsigned a3,
    unsigned b0, unsigned b1)
{
    asm("mma.sync.aligned.m16n8k8.row.col.f32.tf32.tf32.f32 "
        "{%0,%1,%2,%3}, {%4,%5,%6,%7}, {%8,%9}, {%0,%1,%2,%3};"
        : "+f"(c[0]), "+f"(c[1]), "+f"(c[2]), "+f"(c[3])
        : "r"(a0), "r"(a1), "r"(a2), "r"(a3), "r"(b0), "r"(b1));
}

// ---------------------------------------------------------------------------
// tf32 tensor-core GEMM with bias, 2-stage double-buffered smem pipeline:
//   out[M=8192, N=1024] = A[8192,1024] @ W[1024,1024] + bias
// 128x128 block tile, K-tile 32, 256 threads (8 warps, 2x4),
// each warp: 64x32 via 4x4 m16n8k8 fragments.
// ---------------------------------------------------------------------------
#define APAD 36     // conflict-free A fragment loads: bank = 4g + l4
#define BPAD 136    // conflict-free B fragment loads: bank = 8l4 + g
#define ASZ (128 * APAD)
#define BSZ (32 * BPAD)

template <bool SPLIT_HEADS>
__global__ __launch_bounds__(256)
void gemm_tf32_kernel(const float* __restrict__ A,
                      const float* __restrict__ W,
                      const float* __restrict__ bias,
                      float* __restrict__ out)
{
    extern __shared__ unsigned gsm[];
    unsigned* As = gsm;             // [2][128*APAD]
    unsigned* Bs = gsm + 2 * ASZ;   // [2][32*BPAD]

    const int tid    = threadIdx.x;
    const int lane   = tid & 31;
    const int wid    = tid >> 5;
    const int warp_m = wid >> 2;
    const int warp_n = wid & 3;
    const int bm     = blockIdx.y * 128;
    const int bn     = blockIdx.x * 128;
    const int g      = lane >> 2;
    const int l4     = lane & 3;

    // Per-thread staging coordinates
    const int ar = tid >> 3, akc = (tid & 7) << 2;      // A: row, k-col (x4 pages of 256)
    const int bkr = tid >> 5, bnc = (tid & 31) << 2;    // B: k-row, n-col

    float acc[4][4][4];
    #pragma unroll
    for (int mt = 0; mt < 4; mt++)
        #pragma unroll
        for (int nt = 0; nt < 4; nt++)
            #pragma unroll
            for (int i = 0; i < 4; i++) acc[mt][nt][i] = 0.f;

    float4 a4[4], b4[4];
    // Prologue: load K-tile 0
    #pragma unroll
    for (int i = 0; i < 4; i++) {
        const int p = tid + i * 256;
        a4[i] = *(const float4*)(A + (size_t)(bm + (p >> 3)) * 1024 + ((p & 7) << 2));
        b4[i] = *(const float4*)(W + (size_t)(p >> 5) * 1024 + bn + ((p & 31) << 2));
    }
    #pragma unroll
    for (int i = 0; i < 4; i++) {
        const int p = tid + i * 256;
        unsigned* da = &As[(p >> 3) * APAD + ((p & 7) << 2)];
        da[0] = f2tf(a4[i].x); da[1] = f2tf(a4[i].y);
        da[2] = f2tf(a4[i].z); da[3] = f2tf(a4[i].w);
        unsigned* db = &Bs[(p >> 5) * BPAD + ((p & 31) << 2)];
        db[0] = f2tf(b4[i].x); db[1] = f2tf(b4[i].y);
        db[2] = f2tf(b4[i].z); db[3] = f2tf(b4[i].w);
    }
    __syncthreads();

    for (int kt = 0; kt < 32; kt++) {
        const unsigned* Ac = As + (kt & 1) * ASZ;
        const unsigned* Bc = Bs + (kt & 1) * BSZ;

        // Prefetch next K-tile from gmem (latency overlapped with mma below)
        if (kt < 31) {
            const int k0 = (kt + 1) * 32;
            #pragma unroll
            for (int i = 0; i < 4; i++) {
                const int p = tid + i * 256;
                a4[i] = *(const float4*)(A + (size_t)(bm + (p >> 3)) * 1024 + k0 + ((p & 7) << 2));
                b4[i] = *(const float4*)(W + (size_t)(k0 + (p >> 5)) * 1024 + bn + ((p & 31) << 2));
            }
        }

        #pragma unroll
        for (int ks = 0; ks < 4; ks++) {
            unsigned af[4][4], bf[4][2];
            #pragma unroll
            for (int mt = 0; mt < 4; mt++) {
                const int row = warp_m * 64 + mt * 16;
                af[mt][0] = Ac[(row + g)     * APAD + ks * 8 + l4];
                af[mt][1] = Ac[(row + 8 + g) * APAD + ks * 8 + l4];
                af[mt][2] = Ac[(row + g)     * APAD + ks * 8 + l4 + 4];
                af[mt][3] = Ac[(row + 8 + g) * APAD + ks * 8 + l4 + 4];
            }
            #pragma unroll
            for (int nt = 0; nt < 4; nt++) {
                const int col = warp_n * 32 + nt * 8 + g;
                bf[nt][0] = Bc[(ks * 8 + l4)     * BPAD + col];
                bf[nt][1] = Bc[(ks * 8 + 4 + l4) * BPAD + col];
            }
            #pragma unroll
            for (int mt = 0; mt < 4; mt++)
                #pragma unroll
                for (int nt = 0; nt < 4; nt++)
                    mma_tf32(acc[mt][nt],
                             af[mt][0], af[mt][1], af[mt][2], af[mt][3],
                             bf[nt][0], bf[nt][1]);
        }

        // Stage next tile into the other buffer
        if (kt < 31) {
            unsigned* An = As + ((kt + 1) & 1) * ASZ;
            unsigned* Bn = Bs + ((kt + 1) & 1) * BSZ;
            #pragma unroll
            for (int i = 0; i < 4; i++) {
                const int p = tid + i * 256;
                unsigned* da = &An[(p >> 3) * APAD + ((p & 7) << 2)];
                da[0] = f2tf(a4[i].x); da[1] = f2tf(a4[i].y);
                da[2] = f2tf(a4[i].z); da[3] = f2tf(a4[i].w);
                unsigned* db = &Bn[(p >> 5) * BPAD + ((p & 31) << 2)];
                db[0] = f2tf(b4[i].x); db[1] = f2tf(b4[i].y);
                db[2] = f2tf(b4[i].z); db[3] = f2tf(b4[i].w);
            }
        }
        __syncthreads();
    }

    #pragma unroll
    for (int mt = 0; mt < 4; mt++) {
        const int r0 = bm + warp_m * 64 + mt * 16 + g;
        const int r1 = r0 + 8;
        #pragma unroll
        for (int nt = 0; nt < 4; nt++) {
            const int c = bn + warp_n * 32 + nt * 8 + 2 * l4;
            const float bx = bias[c], by = bias[c + 1];
            float2 v0 = make_float2(acc[mt][nt][0] + bx, acc[mt][nt][1] + by);
            float2 v1 = make_float2(acc[mt][nt][2] + bx, acc[mt][nt][3] + by);
            if (SPLIT_HEADS) {
                const int h  = c >> 6, d = c & 63;
                const int b0_ = r0 >> 11, l0_ = r0 & 2047;
                const int b1_ = r1 >> 11, l1_ = r1 & 2047;
                *(float2*)(out + ((size_t)((b0_ * NH + h) * SEQ + l0_)) * DH + d) = v0;
                *(float2*)(out + ((size_t)((b1_ * NH + h) * SEQ + l1_)) * DH + d) = v1;
            } else {
                *(float2*)(out + (size_t)r0 * 1024 + c) = v0;
                *(float2*)(out + (size_t)r1 * 1024 + c) = v1;
            }
        }
    }
}

// ---------------------------------------------------------------------------
// Flash attention (causal) on tf32 mma.m16n8k8.
// 256 threads (8 warps), q-tile 128 (16 rows/warp), kv-tile 64.
// V padded to 72 (bank = 8*l4+g, conflict-free). Per-warp skip of fully
// masked kv tiles. Heavy (late-qt) blocks scheduled first.
// ---------------------------------------------------------------------------
#define PADK 68
#define PADV 72

__global__ __launch_bounds__(256, 2)
void attn_mma_kernel()
{
    extern __shared__ unsigned smu[];
    unsigned* Qs = smu;                    // [128][PADK] tf32, pre-scaled
    unsigned* Ks = Qs + 128 * PADK;        // [64][PADK]
    unsigned* Vs = Ks + 64 * PADK;         // [64][PADV]
    unsigned* Ps = Vs + 64 * PADV;         // [128][PADK] per-warp rows

    const int tid  = threadIdx.x;
    const int lane = tid & 31;
    const int wid  = tid >> 5;        // 0..7
    const int g    = lane >> 2;
    const int l4   = lane & 3;
    const int qt   = gridDim.x - 1 - blockIdx.x;   // heavy blocks first
    const int bh   = blockIdx.y;
    const int m0   = wid * 16;

    const float* Qg = g_Q + ((size_t)bh * SEQ + qt * 128) * DH;
    const float* Kg = g_K + (size_t)bh * SEQ * DH;
    const float* Vg = g_V + (size_t)bh * SEQ * DH;

    // Load Q tile (pre-scaled by 1/sqrt(dh)=0.125) as tf32
    for (int i = tid; i < 128 * 16; i += 256) {
        const int q = i >> 4, d4 = (i & 15) << 2;
        float4 v = *(const float4*)(Qg + q * 64 + d4);
        uint4 t;
        t.x = f2tf(v.x * 0.125f); t.y = f2tf(v.y * 0.125f);
        t.z = f2tf(v.z * 0.125f); t.w = f2tf(v.w * 0.125f);
        *(uint4*)&Qs[q * PADK + d4] = t;
    }
    __syncthreads();

    // Preload Q A-fragments (8 k-steps over d=64)
    unsigned qa[8][4];
    #pragma unroll
    for (int ks = 0; ks < 8; ks++) {
        qa[ks][0] = Qs[(m0 + g)     * PADK + ks * 8 + l4];
        qa[ks][1] = Qs[(m0 + 8 + g) * PADK + ks * 8 + l4];
        qa[ks][2] = Qs[(m0 + g)     * PADK + ks * 8 + l4 + 4];
        qa[ks][3] = Qs[(m0 + 8 + g) * PADK + ks * 8 + l4 + 4];
    }

    float o[8][4];
    #pragma unroll
    for (int nt = 0; nt < 8; nt++)
        #pragma unroll
        for (int i = 0; i < 4; i++) o[nt][i] = 0.f;
    float mrow[2] = {-1e30f, -1e30f};
    float lrow[2] = {0.f, 0.f};

    const int R0  = qt * 128 + m0;    // warp's min global q row
    const int r0g = R0 + g;
    const int r1g = r0g + 8;
    const int ntiles = 2 * qt + 2;

    for (int jt = 0; jt < ntiles; jt++) {
        __syncthreads();   // prev iter's K/V reads done
        for (int i = tid; i < 64 * 16; i += 256) {
            const int r = i >> 4, d4 = (i & 15) << 2;
            float4 kv = *(const float4*)(Kg + (size_t)(jt * 64 + r) * 64 + d4);
            uint4 tk;
            tk.x = f2tf(kv.x); tk.y = f2tf(kv.y);
            tk.z = f2tf(kv.z); tk.w = f2tf(kv.w);
            *(uint4*)&Ks[r * PADK + d4] = tk;
            float4 vv = *(const float4*)(Vg + (size_t)(jt * 64 + r) * 64 + d4);
            uint4 tv;
            tv.x = f2tf(vv.x); tv.y = f2tf(vv.y);
            tv.z = f2tf(vv.z); tv.w = f2tf(vv.w);
            *(uint4*)&Vs[r * PADV + d4] = tv;
        }
        __syncthreads();

        // Skip compute if this warp's 16 rows are entirely above the tile
        if (jt * 64 > R0 + 15) continue;

        // S = Q K^T : per warp 16x64
        float s[8][4];
        #pragma unroll
        for (int nt = 0; nt < 8; nt++)
            #pragma unroll
            for (int i = 0; i < 4; i++) s[nt][i] = 0.f;

        #pragma unroll
        for (int nt = 0; nt < 8; nt++) {
            const unsigned* krow = &Ks[(nt * 8 + g) * PADK];
            #pragma unroll
            for (int ks = 0; ks < 8; ks++) {
                const unsigned b0 = krow[ks * 8 + l4];
                const unsigned b1 = krow[ks * 8 + l4 + 4];
                mma_tf32(s[nt], qa[ks][0], qa[ks][1], qa[ks][2], qa[ks][3], b0, b1);
            }
        }

        // Causal mask (only tiles overlapping the diagonal for this warp)
        if (jt * 64 + 63 > R0) {
            #pragma unroll
            for (int nt = 0; nt < 8; nt++) {
                const int c = jt * 64 + nt * 8 + 2 * l4;
                if (c     > r0g) s[nt][0] = -1e30f;
                if (c + 1 > r0g) s[nt][1] = -1e30f;
                if (c     > r1g) s[nt][2] = -1e30f;
                if (c + 1 > r1g) s[nt][3] = -1e30f;
            }
        }

        // Online softmax (rows live in lane quads -> shfl 1,2 only)
        float mx0 = -1e30f, mx1 = -1e30f;
        #pragma unroll
        for (int nt = 0; nt < 8; nt++) {
            mx0 = fmaxf(mx0, fmaxf(s[nt][0], s[nt][1]));
            mx1 = fmaxf(mx1, fmaxf(s[nt][2], s[nt][3]));
        }
        mx0 = fmaxf(mx0, __shfl_xor_sync(0xffffffffu, mx0, 1));
        mx0 = fmaxf(mx0, __shfl_xor_sync(0xffffffffu, mx0, 2));
        mx1 = fmaxf(mx1, __shfl_xor_sync(0xffffffffu, mx1, 1));
        mx1 = fmaxf(mx1, __shfl_xor_sync(0xffffffffu, mx1, 2));

        const float mn0 = fmaxf(mrow[0], mx0);
        const float mn1 = fmaxf(mrow[1], mx1);
        const float c0 = __expf(mrow[0] - mn0);
        const float c1 = __expf(mrow[1] - mn1);

        float sum0 = 0.f, sum1 = 0.f;
        #pragma unroll
        for (int nt = 0; nt < 8; nt++) {
            s[nt][0] = __expf(s[nt][0] - mn0);
            s[nt][1] = __expf(s[nt][1] - mn0);
            s[nt][2] = __expf(s[nt][2] - mn1);
            s[nt][3] = __expf(s[nt][3] - mn1);
            sum0 += s[nt][0] + s[nt][1];
            sum1 += s[nt][2] + s[nt][3];
        }
        sum0 += __shfl_xor_sync(0xffffffffu, sum0, 1);
        sum0 += __shfl_xor_sync(0xffffffffu, sum0, 2);
        sum1 += __shfl_xor_sync(0xffffffffu, sum1, 1);
        sum1 += __shfl_xor_sync(0xffffffffu, sum1, 2);

        lrow[0] = lrow[0] * c0 + sum0;
        lrow[1] = lrow[1] * c1 + sum1;
        mrow[0] = mn0;
        mrow[1] = mn1;
        #pragma unroll
        for (int nt = 0; nt < 8; nt++) {
            o[nt][0] *= c0; o[nt][1] *= c0;
            o[nt][2] *= c1; o[nt][3] *= c1;
        }

        // Store P (tf32) to this warp's rows; no cross-warp dependency
        #pragma unroll
        for (int nt = 0; nt < 8; nt++) {
            uint2 p0 = make_uint2(f2tf(s[nt][0]), f2tf(s[nt][1]));
            uint2 p1 = make_uint2(f2tf(s[nt][2]), f2tf(s[nt][3]));
            *(uint2*)&Ps[(m0 + g)     * PADK + nt * 8 + 2 * l4] = p0;
            *(uint2*)&Ps[(m0 + 8 + g) * PADK + nt * 8 + 2 * l4] = p1;
        }
        __syncwarp();

        // O += P @ V
        #pragma unroll
        for (int ks = 0; ks < 8; ks++) {
            const unsigned pa0 = Ps[(m0 + g)     * PADK + ks * 8 + l4];
            const unsigned pa1 = Ps[(m0 + 8 + g) * PADK + ks * 8 + l4];
            const unsigned pa2 = Ps[(m0 + g)     * PADK + ks * 8 + l4 + 4];
            const unsigned pa3 = Ps[(m0 + 8 + g) * PADK + ks * 8 + l4 + 4];
            const unsigned* v0 = &Vs[(ks * 8 + l4)     * PADV];
            const unsigned* v1 = &Vs[(ks * 8 + l4 + 4) * PADV];
            #pragma unroll
            for (int nt = 0; nt < 8; nt++)
                mma_tf32(o[nt], pa0, pa1, pa2, pa3, v0[nt * 8 + g], v1[nt * 8 + g]);
        }
    }

    // Epilogue: normalize, write ctx [b, l, h*64+d]
    const int b_ = bh >> 4;
    const int h_ = bh & 15;
    const float inv0 = 1.f / lrow[0];
    const float inv1 = 1.f / lrow[1];
    float* c0p = g_ctx + ((size_t)(b_ * SEQ + qt * 128 + m0 + g))     * DMODEL + h_ * 64;
    float* c1p = g_ctx + ((size_t)(b_ * SEQ + qt * 128 + m0 + 8 + g)) * DMODEL + h_ * 64;
    #pragma unroll
    for (int nt = 0; nt < 8; nt++) {
        *(float2*)(c0p + nt * 8 + 2 * l4) = make_float2(o[nt][0] * inv0, o[nt][1] * inv0);
        *(float2*)(c1p + nt * 8 + 2 * l4) = make_float2(o[nt][2] * inv1, o[nt][3] * inv1);
    }
}

// ---------------------------------------------------------------------------
extern "C" void kernel_launch(void* const* d_in, const int* in_sizes, int n_in,
                              void* d_out, int out_size)
{
    const float* x  = (const float*)d_in[0];
    const float* Wq = (const float*)d_in[2];
    const float* bq = (const float*)d_in[3];
    const float* Wk = (const float*)d_in[4];
    const float* bk = (const float*)d_in[5];
    const float* Wv = (const float*)d_in[6];
    const float* bv = (const float*)d_in[7];
    const float* Wo = (const float*)d_in[8];
    const float* bo = (const float*)d_in[9];
    float* out = (float*)d_out;

    float *qp, *kp, *vp, *cp;
    cudaGetSymbolAddress((void**)&qp, g_Q);
    cudaGetSymbolAddress((void**)&kp, g_K);
    cudaGetSymbolAddress((void**)&vp, g_V);
    cudaGetSymbolAddress((void**)&cp, g_ctx);

    const int gemm_smem = 2 * (ASZ + BSZ) * (int)sizeof(unsigned);   // 71680
    cudaFuncSetAttribute(gemm_tf32_kernel<true>,
                         cudaFuncAttributeMaxDynamicSharedMemorySize, gemm_smem);
    cudaFuncSetAttribute(gemm_tf32_kernel<false>,
                         cudaFuncAttributeMaxDynamicSharedMemorySize, gemm_smem);

    const dim3 ggrid(8, 64);   // N/128, M/128
    gemm_tf32_kernel<true><<<ggrid, 256, gemm_smem>>>(x, Wq, bq, qp);
    gemm_tf32_kernel<true><<<ggrid, 256, gemm_smem>>>(x, Wk, bk, kp);
    gemm_tf32_kernel<true><<<ggrid, 256, gemm_smem>>>(x, Wv, bv, vp);

    const int attn_smem =
        (128 * PADK + 64 * PADK + 64 * PADV + 128 * PADK) * (int)sizeof(unsigned); // 105472
    cudaFuncSetAttribute(attn_mma_kernel,
                         cudaFuncAttributeMaxDynamicSharedMemorySize, attn_smem);
    attn_mma_kernel<<<dim3(16, 64), 256, attn_smem>>>();

    gemm_tf32_kernel<false><<<ggrid, 256, gemm_smem>>>(cp, Wo, bo, out);
}

// round 6
// speedup vs baseline: 6.2505x; 1.9829x over previous
#include <cuda_runtime.h>
#include <cuda_fp16.h>
#include <math.h>
#include <stdint.h>

#define BATCH 4
#define SEQ   2048
#define DMODEL 1024
#define NH    16
#define DH    64

// Scratch (device globals; allocation-free per harness rules)
__device__ __half g_X  [BATCH * SEQ * DMODEL];   // x, fp16
__device__ __half g_WqT[DMODEL * DMODEL];        // W^T, fp16
__device__ __half g_WkT[DMODEL * DMODEL];
__device__ __half g_WvT[DMODEL * DMODEL];
__device__ __half g_WoT[DMODEL * DMODEL];
__device__ __half g_Q  [BATCH * NH * SEQ * DH];  // [b,h,l,d]
__device__ __half g_K  [BATCH * NH * SEQ * DH];
__device__ __half g_V  [BATCH * NH * SEQ * DH];
__device__ __half g_ctx[BATCH * SEQ * DMODEL];   // [b,l,h*64+d]

// ---------------------------------------------------------------------------
// helpers
// ---------------------------------------------------------------------------
__device__ __forceinline__ uint32_t smem_u32(const void* p) {
    uint32_t a;
    asm("{ .reg .u64 t; cvta.to.shared.u64 t, %1; cvt.u32.u64 %0, t; }"
        : "=r"(a) : "l"(p));
    return a;
}

__device__ __forceinline__ void mma_f16(float* c,
    uint32_t a0, uint32_t a1, uint32_t a2, uint32_t a3,
    uint32_t b0, uint32_t b1)
{
    asm("mma.sync.aligned.m16n8k16.row.col.f32.f16.f16.f32 "
        "{%0,%1,%2,%3}, {%4,%5,%6,%7}, {%8,%9}, {%0,%1,%2,%3};"
        : "+f"(c[0]), "+f"(c[1]), "+f"(c[2]), "+f"(c[3])
        : "r"(a0), "r"(a1), "r"(a2), "r"(a3), "r"(b0), "r"(b1));
}

__device__ __forceinline__ void ldsm4(uint32_t* r, uint32_t a) {
    asm volatile("ldmatrix.sync.aligned.m8n8.x4.shared.b16 {%0,%1,%2,%3}, [%4];"
        : "=r"(r[0]), "=r"(r[1]), "=r"(r[2]), "=r"(r[3]) : "r"(a));
}
__device__ __forceinline__ void ldsm4t(uint32_t* r, uint32_t a) {
    asm volatile("ldmatrix.sync.aligned.m8n8.x4.trans.shared.b16 {%0,%1,%2,%3}, [%4];"
        : "=r"(r[0]), "=r"(r[1]), "=r"(r[2]), "=r"(r[3]) : "r"(a));
}

__device__ __forceinline__ uint32_t packh2(float a, float b) {
    __half2 h = __floats2half2_rn(a, b);       // a -> low half
    return *reinterpret_cast<uint32_t*>(&h);
}

// ---------------------------------------------------------------------------
// Pre-pass: x -> fp16; W -> W^T fp16
// ---------------------------------------------------------------------------
__global__ __launch_bounds__(256)
void conv_half_kernel(const float4* __restrict__ in, uint2* __restrict__ out, int n4)
{
    int i = blockIdx.x * 256 + threadIdx.x;
    if (i < n4) {
        float4 v = in[i];
        uint2 o;
        o.x = packh2(v.x, v.y);
        o.y = packh2(v.z, v.w);
        out[i] = o;
    }
}

__global__ __launch_bounds__(256)
void transpose_half_kernel(const float* __restrict__ W, __half* __restrict__ Wt)
{
    __shared__ float s[32][33];
    const int tx = threadIdx.x, ty = threadIdx.y;    // 32 x 8
    const int n0 = blockIdx.x * 32, k0 = blockIdx.y * 32;
    #pragma unroll
    for (int i = 0; i < 4; i++)
        s[ty + 8 * i][tx] = W[(size_t)(k0 + ty + 8 * i) * DMODEL + n0 + tx];
    __syncthreads();
    #pragma unroll
    for (int i = 0; i < 4; i++)
        Wt[(size_t)(n0 + ty + 8 * i) * DMODEL + k0 + tx] = __float2half(s[tx][ty + 8 * i]);
}

// ---------------------------------------------------------------------------
// fp16 GEMM: out[8192,1024] = A @ W + bias     (A fp16 K-major, Bt = W^T fp16)
// 128x128 tile, K-tile 32, 256 threads (8 warps 2x4), warp 64x32,
// m16n8k16 with ldmatrix fragment loads, double-buffered smem.
// Smem row = 32 halves padded to 40 (80 B, 16B-multiple, conflict-free LDSM).
// ---------------------------------------------------------------------------
#define GEMM_BUF 10240          // 128 rows * 80 B
#define GEMM_SMEM (4 * GEMM_BUF)

template <bool SPLIT>
__global__ __launch_bounds__(256, 2)
void gemm_f16_kernel(const __half* __restrict__ A, const __half* __restrict__ Bt,
                     const float* __restrict__ bias, void* __restrict__ outv)
{
    extern __shared__ char smem[];
    const uint32_t sb = smem_u32(smem);
    const int tid = threadIdx.x, lane = tid & 31, wid = tid >> 5;
    const int warp_m = wid >> 2, warp_n = wid & 3;
    const int bm = blockIdx.y * 128, bn = blockIdx.x * 128;
    const int g = lane >> 2, l4 = lane & 3;
    const int sect = lane >> 3, li = lane & 7;

    // ldmatrix per-lane base byte offsets (within a buffer)
    const uint32_t aoff = (uint32_t)(warp_m * 64 + (sect & 1) * 8 + li) * 80
                        + (sect >> 1) * 16;
    const uint32_t boff = (uint32_t)(warp_n * 32 + (sect >> 1) * 8 + li) * 80
                        + (sect & 1) * 16;

    // staging coords: 512 uint4 per matrix, 2 per thread
    float acc[4][4][4];
    #pragma unroll
    for (int mt = 0; mt < 4; mt++)
        #pragma unroll
        for (int nt = 0; nt < 4; nt++)
            #pragma unroll
            for (int i = 0; i < 4; i++) acc[mt][nt][i] = 0.f;

    // Prologue: stage K-tile 0 into buffer 0
    #pragma unroll
    for (int i = 0; i < 2; i++) {
        const int p = tid + i * 256;
        const int row = p >> 2, kc = (p & 3) * 8;
        uint4 va = *(const uint4*)(A  + (size_t)(bm + row) * 1024 + kc);
        *(uint4*)(smem + row * 80 + kc * 2) = va;
        uint4 vb = *(const uint4*)(Bt + (size_t)(bn + row) * 1024 + kc);
        *(uint4*)(smem + 2 * GEMM_BUF + row * 80 + kc * 2) = vb;
    }
    __syncthreads();

    uint4 pa[2], pb[2];
    for (int kt = 0; kt < 32; kt++) {
        const uint32_t abase = sb + (kt & 1) * GEMM_BUF + aoff;
        const uint32_t bbase = sb + 2 * GEMM_BUF + (kt & 1) * GEMM_BUF + boff;

        if (kt < 31) {
            const int k0 = (kt + 1) * 32;
            #pragma unroll
            for (int i = 0; i < 2; i++) {
                const int p = tid + i * 256;
                const int row = p >> 2, kc = (p & 3) * 8;
                pa[i] = *(const uint4*)(A  + (size_t)(bm + row) * 1024 + k0 + kc);
                pb[i] = *(const uint4*)(Bt + (size_t)(bn + row) * 1024 + k0 + kc);
            }
        }

        #pragma unroll
        for (int ks = 0; ks < 2; ks++) {
            uint32_t af[4][4], bf[2][4];
            #pragma unroll
            for (int mt = 0; mt < 4; mt++)
                ldsm4(af[mt], abase + mt * 16 * 80 + ks * 32);
            #pragma unroll
            for (int t = 0; t < 2; t++)
                ldsm4(bf[t], bbase + t * 16 * 80 + ks * 32);
            #pragma unroll
            for (int mt = 0; mt < 4; mt++)
                #pragma unroll
                for (int nt = 0; nt < 4; nt++)
                    mma_f16(acc[mt][nt],
                            af[mt][0], af[mt][1], af[mt][2], af[mt][3],
                            bf[nt >> 1][(nt & 1) * 2], bf[nt >> 1][(nt & 1) * 2 + 1]);
        }

        if (kt < 31) {
            char* Ab = smem + ((kt + 1) & 1) * GEMM_BUF;
            char* Bb = smem + 2 * GEMM_BUF + ((kt + 1) & 1) * GEMM_BUF;
            #pragma unroll
            for (int i = 0; i < 2; i++) {
                const int p = tid + i * 256;
                const int row = p >> 2, kc = (p & 3) * 8;
                *(uint4*)(Ab + row * 80 + kc * 2) = pa[i];
                *(uint4*)(Bb + row * 80 + kc * 2) = pb[i];
            }
        }
        __syncthreads();
    }

    // Epilogue
    #pragma unroll
    for (int mt = 0; mt < 4; mt++) {
        const int r0 = bm + warp_m * 64 + mt * 16 + g;
        const int r1 = r0 + 8;
        #pragma unroll
        for (int nt = 0; nt < 4; nt++) {
            const int c = bn + warp_n * 32 + nt * 8 + 2 * l4;
            const float bx = bias[c], by = bias[c + 1];
            const float v0x = acc[mt][nt][0] + bx, v0y = acc[mt][nt][1] + by;
            const float v1x = acc[mt][nt][2] + bx, v1y = acc[mt][nt][3] + by;
            if (SPLIT) {
                const int h = c >> 6, d = c & 63;
                const int b0_ = r0 >> 11, l0_ = r0 & 2047;
                const int b1_ = r1 >> 11, l1_ = r1 & 2047;
                __half* oh = (__half*)outv;
                *(uint32_t*)(oh + ((size_t)((b0_ * NH + h) * SEQ + l0_)) * DH + d) =
                    packh2(v0x, v0y);
                *(uint32_t*)(oh + ((size_t)((b1_ * NH + h) * SEQ + l1_)) * DH + d) =
                    packh2(v1x, v1y);
            } else {
                float* of = (float*)outv;
                *(float2*)(of + (size_t)r0 * 1024 + c) = make_float2(v0x, v0y);
                *(float2*)(of + (size_t)r1 * 1024 + c) = make_float2(v1x, v1y);
            }
        }
    }
}

// ---------------------------------------------------------------------------
// Flash attention (causal), fp16 m16n8k16, P kept in registers.
// 256 threads (8 warps), q-tile 128 (16 rows/warp), kv-tile 64.
// Smem: Q[128][72h], K[64][72h], V[64][72h] (144 B rows, conflict-free LDSM).
// ---------------------------------------------------------------------------
#define ATT_QB 0
#define ATT_KB 18432
#define ATT_VB 27648
#define ATT_SMEM 36864

__global__ __launch_bounds__(256, 2)
void attn_f16_kernel()
{
    extern __shared__ char smc[];
    const uint32_t sb = smem_u32(smc);

    const int tid  = threadIdx.x;
    const int lane = tid & 31;
    const int wid  = tid >> 5;
    const int g    = lane >> 2;
    const int l4   = lane & 3;
    const int sect = lane >> 3, li = lane & 7;
    const int qt   = gridDim.x - 1 - blockIdx.x;   // heavy blocks first
    const int bh   = blockIdx.y;
    const int m0   = wid * 16;

    const __half* Qg = g_Q + ((size_t)bh * SEQ + qt * 128) * DH;
    const __half* Kg = g_K + (size_t)bh * SEQ * DH;
    const __half* Vg = g_V + (size_t)bh * SEQ * DH;

    // ldmatrix per-lane byte base offsets
    const uint32_t qaddr0 = sb + ATT_QB
        + (uint32_t)(m0 + (sect & 1) * 8 + li) * 144 + (sect >> 1) * 16;
    const uint32_t kaddr0 = sb + ATT_KB
        + (uint32_t)((sect >> 1) * 8 + li) * 144 + (sect & 1) * 16;
    const uint32_t vaddr0 = sb + ATT_VB
        + (uint32_t)((sect & 1) * 8 + li) * 144 + (sect >> 1) * 16;

    // Stage Q (scaled by 0.125, exact in fp16)
    const __half2 scl = __half2half2(__float2half(0.125f));
    #pragma unroll
    for (int i = 0; i < 4; i++) {
        const int p = tid + i * 256;                // 0..1023
        const int row = p >> 3, dc = (p & 7) * 8;
        uint4 v = *(const uint4*)(Qg + row * 64 + dc);
        __half2* h = (__half2*)&v;
        h[0] = __hmul2(h[0], scl); h[1] = __hmul2(h[1], scl);
        h[2] = __hmul2(h[2], scl); h[3] = __hmul2(h[3], scl);
        *(uint4*)(smc + ATT_QB + row * 144 + dc * 2) = v;
    }
    __syncthreads();

    // Preload Q A-fragments: 4 k16-steps over d=64
    uint32_t qa[4][4];
    #pragma unroll
    for (int ks = 0; ks < 4; ks++) ldsm4(qa[ks], qaddr0 + ks * 32);

    float o[8][4];
    #pragma unroll
    for (int nt = 0; nt < 8; nt++)
        #pragma unroll
        for (int i = 0; i < 4; i++) o[nt][i] = 0.f;
    float mrow[2] = {-1e30f, -1e30f};
    float lrow[2] = {0.f, 0.f};

    const int R0  = qt * 128 + m0;
    const int r0g = R0 + g;
    const int r1g = r0g + 8;
    const int ntiles = 2 * qt + 2;

    for (int jt = 0; jt < ntiles; jt++) {
        __syncthreads();   // prev iter's K/V fragment reads done
        #pragma unroll
        for (int i = 0; i < 2; i++) {
            const int p = tid + i * 256;            // 0..511
            const int row = p >> 3, dc = (p & 7) * 8;
            *(uint4*)(smc + ATT_KB + row * 144 + dc * 2) =
                *(const uint4*)(Kg + (size_t)(jt * 64 + row) * 64 + dc);
            *(uint4*)(smc + ATT_VB + row * 144 + dc * 2) =
                *(const uint4*)(Vg + (size_t)(jt * 64 + row) * 64 + dc);
        }
        __syncthreads();

        if (jt * 64 > R0 + 15) continue;   // warp fully above diagonal

        // S = Q K^T : 16x64 per warp
        float s[8][4];
        #pragma unroll
        for (int nt = 0; nt < 8; nt++)
            #pragma unroll
            for (int i = 0; i < 4; i++) s[nt][i] = 0.f;

        #pragma unroll
        for (int t = 0; t < 4; t++) {
            #pragma unroll
            for (int ks = 0; ks < 4; ks++) {
                uint32_t kb[4];
                ldsm4(kb, kaddr0 + t * 16 * 144 + ks * 32);
                mma_f16(s[2 * t],     qa[ks][0], qa[ks][1], qa[ks][2], qa[ks][3],
                        kb[0], kb[1]);
                mma_f16(s[2 * t + 1], qa[ks][0], qa[ks][1], qa[ks][2], qa[ks][3],
                        kb[2], kb[3]);
            }
        }

        // Causal mask (tiles overlapping this warp's diagonal)
        if (jt * 64 + 63 > R0) {
            #pragma unroll
            for (int nt = 0; nt < 8; nt++) {
                const int c = jt * 64 + nt * 8 + 2 * l4;
                if (c     > r0g) s[nt][0] = -1e30f;
                if (c + 1 > r0g) s[nt][1] = -1e30f;
                if (c     > r1g) s[nt][2] = -1e30f;
                if (c + 1 > r1g) s[nt][3] = -1e30f;
            }
        }

        // Online softmax (rows in lane quads)
        float mx0 = -1e30f, mx1 = -1e30f;
        #pragma unroll
        for (int nt = 0; nt < 8; nt++) {
            mx0 = fmaxf(mx0, fmaxf(s[nt][0], s[nt][1]));
            mx1 = fmaxf(mx1, fmaxf(s[nt][2], s[nt][3]));
        }
        mx0 = fmaxf(mx0, __shfl_xor_sync(0xffffffffu, mx0, 1));
        mx0 = fmaxf(mx0, __shfl_xor_sync(0xffffffffu, mx0, 2));
        mx1 = fmaxf(mx1, __shfl_xor_sync(0xffffffffu, mx1, 1));
        mx1 = fmaxf(mx1, __shfl_xor_sync(0xffffffffu, mx1, 2));

        const float mn0 = fmaxf(mrow[0], mx0);
        const float mn1 = fmaxf(mrow[1], mx1);
        const float c0 = __expf(mrow[0] - mn0);
        const float c1 = __expf(mrow[1] - mn1);

        float sum0 = 0.f, sum1 = 0.f;
        #pragma unroll
        for (int nt = 0; nt < 8; nt++) {
            s[nt][0] = __expf(s[nt][0] - mn0);
            s[nt][1] = __expf(s[nt][1] - mn0);
            s[nt][2] = __expf(s[nt][2] - mn1);
            s[nt][3] = __expf(s[nt][3] - mn1);
            sum0 += s[nt][0] + s[nt][1];
            sum1 += s[nt][2] + s[nt][3];
        }
        sum0 += __shfl_xor_sync(0xffffffffu, sum0, 1);
        sum0 += __shfl_xor_sync(0xffffffffu, sum0, 2);
        sum1 += __shfl_xor_sync(0xffffffffu, sum1, 1);
        sum1 += __shfl_xor_sync(0xffffffffu, sum1, 2);

        lrow[0] = lrow[0] * c0 + sum0;
        lrow[1] = lrow[1] * c1 + sum1;
        mrow[0] = mn0;
        mrow[1] = mn1;
        #pragma unroll
        for (int nt = 0; nt < 8; nt++) {
            o[nt][0] *= c0; o[nt][1] *= c0;
            o[nt][2] *= c1; o[nt][3] *= c1;
        }

        // P -> fp16 A-fragments in registers (C-frag layout == A-frag layout)
        uint32_t ph[4][4];
        #pragma unroll
        for (int ks = 0; ks < 4; ks++) {
            ph[ks][0] = packh2(s[2 * ks][0],     s[2 * ks][1]);
            ph[ks][1] = packh2(s[2 * ks][2],     s[2 * ks][3]);
            ph[ks][2] = packh2(s[2 * ks + 1][0], s[2 * ks + 1][1]);
            ph[ks][3] = packh2(s[2 * ks + 1][2], s[2 * ks + 1][3]);
        }

        // O += P @ V : V B-fragments via ldmatrix.trans
        #pragma unroll
        for (int t = 0; t < 4; t++) {
            #pragma unroll
            for (int ks = 0; ks < 4; ks++) {
                uint32_t vb[4];
                ldsm4t(vb, vaddr0 + ks * 16 * 144 + t * 32);
                mma_f16(o[2 * t],     ph[ks][0], ph[ks][1], ph[ks][2], ph[ks][3],
                        vb[0], vb[1]);
                mma_f16(o[2 * t + 1], ph[ks][0], ph[ks][1], ph[ks][2], ph[ks][3],
                        vb[2], vb[3]);
            }
        }
    }

    // Epilogue: normalize, write ctx as fp16
    const int b_ = bh >> 4;
    const int h_ = bh & 15;
    const float inv0 = 1.f / lrow[0];
    const float inv1 = 1.f / lrow[1];
    __half* c0p = g_ctx + ((size_t)(b_ * SEQ + qt * 128 + m0 + g))     * DMODEL + h_ * 64;
    __half* c1p = g_ctx + ((size_t)(b_ * SEQ + qt * 128 + m0 + 8 + g)) * DMODEL + h_ * 64;
    #pragma unroll
    for (int nt = 0; nt < 8; nt++) {
        *(uint32_t*)(c0p + nt * 8 + 2 * l4) = packh2(o[nt][0] * inv0, o[nt][1] * inv0);
        *(uint32_t*)(c1p + nt * 8 + 2 * l4) = packh2(o[nt][2] * inv1, o[nt][3] * inv1);
    }
}

// ---------------------------------------------------------------------------
extern "C" void kernel_launch(void* const* d_in, const int* in_sizes, int n_in,
                              void* d_out, int out_size)
{
    const float* x  = (const float*)d_in[0];
    const float* Wq = (const float*)d_in[2];
    const float* bq = (const float*)d_in[3];
    const float* Wk = (const float*)d_in[4];
    const float* bk = (const float*)d_in[5];
    const float* Wv = (const float*)d_in[6];
    const float* bv = (const float*)d_in[7];
    const float* Wo = (const float*)d_in[8];
    const float* bo = (const float*)d_in[9];
    float* out = (float*)d_out;

    __half *xp, *wqt, *wkt, *wvt, *wot, *qp, *kp, *vp, *cp;
    cudaGetSymbolAddress((void**)&xp,  g_X);
    cudaGetSymbolAddress((void**)&wqt, g_WqT);
    cudaGetSymbolAddress((void**)&wkt, g_WkT);
    cudaGetSymbolAddress((void**)&wvt, g_WvT);
    cudaGetSymbolAddress((void**)&wot, g_WoT);
    cudaGetSymbolAddress((void**)&qp,  g_Q);
    cudaGetSymbolAddress((void**)&kp,  g_K);
    cudaGetSymbolAddress((void**)&vp,  g_V);
    cudaGetSymbolAddress((void**)&cp,  g_ctx);

    // Pre-pass
    const int n4 = BATCH * SEQ * DMODEL / 4;
    conv_half_kernel<<<(n4 + 255) / 256, 256>>>((const float4*)x, (uint2*)xp, n4);
    dim3 tgrid(32, 32), tblk(32, 8);
    transpose_half_kernel<<<tgrid, tblk>>>(Wq, wqt);
    transpose_half_kernel<<<tgrid, tblk>>>(Wk, wkt);
    transpose_half_kernel<<<tgrid, tblk>>>(Wv, wvt);
    transpose_half_kernel<<<tgrid, tblk>>>(Wo, wot);

    cudaFuncSetAttribute(gemm_f16_kernel<true>,
                         cudaFuncAttributeMaxDynamicSharedMemorySize, GEMM_SMEM);
    cudaFuncSetAttribute(gemm_f16_kernel<false>,
                         cudaFuncAttributeMaxDynamicSharedMemorySize, GEMM_SMEM);

    const dim3 ggrid(8, 64);   // N/128, M/128
    gemm_f16_kernel<true><<<ggrid, 256, GEMM_SMEM>>>(xp, wqt, bq, qp);
    gemm_f16_kernel<true><<<ggrid, 256, GEMM_SMEM>>>(xp, wkt, bk, kp);
    gemm_f16_kernel<true><<<ggrid, 256, GEMM_SMEM>>>(xp, wvt, bv, vp);

    cudaFuncSetAttribute(attn_f16_kernel,
                         cudaFuncAttributeMaxDynamicSharedMemorySize, ATT_SMEM);
    attn_f16_kernel<<<dim3(16, 64), 256, ATT_SMEM>>>();

    gemm_f16_kernel<false><<<ggrid, 256, GEMM_SMEM>>>(cp, wot, bo, out);
}

// round 11
// speedup vs baseline: 6.8255x; 1.0920x over previous
#include <cuda_runtime.h>
#include <cuda_fp16.h>
#include <math.h>
#include <stdint.h>

#define BATCH 4
#define SEQ   2048
#define DMODEL 1024
#define NH    16
#define DH    64

// Scratch (device globals; allocation-free per harness rules)
__device__ __half g_X [BATCH * SEQ * DMODEL];   // x, fp16
__device__ __half g_Wq[DMODEL * DMODEL];        // W fp16, natural [k][n]
__device__ __half g_Wk[DMODEL * DMODEL];
__device__ __half g_Wv[DMODEL * DMODEL];
__device__ __half g_Wo[DMODEL * DMODEL];
__device__ __half g_Q [BATCH * NH * SEQ * DH];  // [b,h,l,d]
__device__ __half g_K [BATCH * NH * SEQ * DH];
__device__ __half g_V [BATCH * NH * SEQ * DH];
__device__ __half g_ctx[BATCH * SEQ * DMODEL];  // [b,l,h*64+d]

// ---------------------------------------------------------------------------
// helpers
// ---------------------------------------------------------------------------
__device__ __forceinline__ uint32_t smem_u32(const void* p) {
    uint32_t a;
    asm("{ .reg .u64 t; cvta.to.shared.u64 t, %1; cvt.u32.u64 %0, t; }"
        : "=r"(a) : "l"(p));
    return a;
}

__device__ __forceinline__ void mma_f16(float* c,
    uint32_t a0, uint32_t a1, uint32_t a2, uint32_t a3,
    uint32_t b0, uint32_t b1)
{
    asm("mma.sync.aligned.m16n8k16.row.col.f32.f16.f16.f32 "
        "{%0,%1,%2,%3}, {%4,%5,%6,%7}, {%8,%9}, {%0,%1,%2,%3};"
        : "+f"(c[0]), "+f"(c[1]), "+f"(c[2]), "+f"(c[3])
        : "r"(a0), "r"(a1), "r"(a2), "r"(a3), "r"(b0), "r"(b1));
}

__device__ __forceinline__ void ldsm4(uint32_t* r, uint32_t a) {
    asm volatile("ldmatrix.sync.aligned.m8n8.x4.shared.b16 {%0,%1,%2,%3}, [%4];"
        : "=r"(r[0]), "=r"(r[1]), "=r"(r[2]), "=r"(r[3]) : "r"(a));
}
__device__ __forceinline__ void ldsm4t(uint32_t* r, uint32_t a) {
    asm volatile("ldmatrix.sync.aligned.m8n8.x4.trans.shared.b16 {%0,%1,%2,%3}, [%4];"
        : "=r"(r[0]), "=r"(r[1]), "=r"(r[2]), "=r"(r[3]) : "r"(a));
}

__device__ __forceinline__ uint32_t packh2(float a, float b) {
    __half2 h = __floats2half2_rn(a, b);
    return *reinterpret_cast<uint32_t*>(&h);
}

__device__ __forceinline__ void cpa16(uint32_t dst, const void* src) {
    asm volatile("cp.async.cg.shared.global [%0], [%1], 16;"
                 :: "r"(dst), "l"(src) : "memory");
}
#define CP_COMMIT() asm volatile("cp.async.commit_group;" ::: "memory")
#define CP_WAIT(n)  asm volatile("cp.async.wait_group %0;" :: "n"(n) : "memory")

// ---------------------------------------------------------------------------
// Pre-pass: elementwise fp32 -> fp16 (x and the 4 weight matrices; no transpose)
// ---------------------------------------------------------------------------
__global__ __launch_bounds__(256)
void conv_half_kernel(const float4* __restrict__ in, uint2* __restrict__ out, int n4)
{
    int i = blockIdx.x * 256 + threadIdx.x;
    if (i < n4) {
        float4 v = in[i];
        uint2 o;
        o.x = packh2(v.x, v.y);
        o.y = packh2(v.z, v.w);
        out[i] = o;
    }
}

// ---------------------------------------------------------------------------
// fp16 GEMM: out[8192,1024] = A @ W + bias
// A fp16 [8192][1024] K-major; W fp16 [1024][1024] natural [k][n] (B-frags via
// ldmatrix.trans). 128x128 tile, K-tile 32, 256 threads (8 warps 2x4),
// 3-stage cp.async pipeline, one __syncthreads per K-tile.
// A rows padded to 80 B; W k-rows padded to 272 B (both conflict-free LDSM).
// ---------------------------------------------------------------------------
#define GA_BUF 10240             // 128 * 80
#define GB_BUF 8704              // 32 * 272
#define GB_BASE (3 * GA_BUF)     // 30720
#define GEMM_SMEM (3 * GA_BUF + 3 * GB_BUF)   // 56832

__device__ __forceinline__ void gemm_stage(
    uint32_t sb, const __half* __restrict__ A, const __half* __restrict__ W,
    int bm, int bn, int kt, int tid)
{
    const int k0 = kt * 32;
    const int buf = kt % 3;
    const uint32_t ab = sb + buf * GA_BUF;
    const uint32_t bb = sb + GB_BASE + buf * GB_BUF;
    #pragma unroll
    for (int i = 0; i < 2; i++) {
        const int p = tid + i * 256;
        // A: row = p>>2 (128), kc16 = p&3
        cpa16(ab + (p >> 2) * 80 + (p & 3) * 16,
              A + (size_t)(bm + (p >> 2)) * 1024 + k0 + (p & 3) * 8);
        // B: k-row = p>>4 (32), c16 = p&15
        cpa16(bb + (p >> 4) * 272 + (p & 15) * 16,
              W + (size_t)(k0 + (p >> 4)) * 1024 + bn + (p & 15) * 8);
    }
    CP_COMMIT();
}

template <bool SPLIT>
__global__ __launch_bounds__(256, 2)
void gemm_f16_kernel(const __half* __restrict__ A, const __half* __restrict__ W,
                     const float* __restrict__ bias, void* __restrict__ outv)
{
    extern __shared__ char smem[];
    const uint32_t sb = smem_u32(smem);
    const int tid = threadIdx.x, lane = tid & 31, wid = tid >> 5;
    const int warp_m = wid >> 2, warp_n = wid & 3;
    const int bm = blockIdx.y * 128, bn = blockIdx.x * 128;
    const int g = lane >> 2, l4 = lane & 3;
    const int sect = lane >> 3, li = lane & 7;

    // ldmatrix per-lane base offsets within a buffer
    const uint32_t aoff = (uint32_t)(warp_m * 64 + (sect & 1) * 8 + li) * 80
                        + (sect >> 1) * 16;
    const uint32_t boff = (uint32_t)((sect & 1) * 8 + li) * 272
                        + (sect >> 1) * 16 + warp_n * 64;

    float acc[4][4][4];
    #pragma unroll
    for (int mt = 0; mt < 4; mt++)
        #pragma unroll
        for (int nt = 0; nt < 4; nt++)
            #pragma unroll
            for (int i = 0; i < 4; i++) acc[mt][nt][i] = 0.f;

    // Prologue: stage tiles 0,1
    gemm_stage(sb, A, W, bm, bn, 0, tid);
    gemm_stage(sb, A, W, bm, bn, 1, tid);

    for (int kt = 0; kt < 32; kt++) {
        if (kt >= 30) { CP_WAIT(0); } else { CP_WAIT(1); }
        __syncthreads();
        if (kt < 30) gemm_stage(sb, A, W, bm, bn, kt + 2, tid);

        const int buf = kt % 3;
        const uint32_t abase = sb + buf * GA_BUF + aoff;
        const uint32_t bbase = sb + GB_BASE + buf * GB_BUF + boff;

        #pragma unroll
        for (int ks = 0; ks < 2; ks++) {
            uint32_t af[4][4], bf[2][4];
            #pragma unroll
            for (int mt = 0; mt < 4; mt++)
                ldsm4(af[mt], abase + mt * 16 * 80 + ks * 32);
            #pragma unroll
            for (int t = 0; t < 2; t++)
                ldsm4t(bf[t], bbase + ks * 16 * 272 + t * 32);
            #pragma unroll
            for (int mt = 0; mt < 4; mt++)
                #pragma unroll
                for (int nt = 0; nt < 4; nt++)
                    mma_f16(acc[mt][nt],
                            af[mt][0], af[mt][1], af[mt][2], af[mt][3],
                            bf[nt >> 1][(nt & 1) * 2], bf[nt >> 1][(nt & 1) * 2 + 1]);
        }
    }

    // Epilogue
    #pragma unroll
    for (int mt = 0; mt < 4; mt++) {
        const int r0 = bm + warp_m * 64 + mt * 16 + g;
        const int r1 = r0 + 8;
        #pragma unroll
        for (int nt = 0; nt < 4; nt++) {
            const int c = bn + warp_n * 32 + nt * 8 + 2 * l4;
            const float bx = bias[c], by = bias[c + 1];
            const float v0x = acc[mt][nt][0] + bx, v0y = acc[mt][nt][1] + by;
            const float v1x = acc[mt][nt][2] + bx, v1y = acc[mt][nt][3] + by;
            if (SPLIT) {
                const int h = c >> 6, d = c & 63;
                const int b0_ = r0 >> 11, l0_ = r0 & 2047;
                const int b1_ = r1 >> 11, l1_ = r1 & 2047;
                __half* oh = (__half*)outv;
                *(uint32_t*)(oh + ((size_t)((b0_ * NH + h) * SEQ + l0_)) * DH + d) =
                    packh2(v0x, v0y);
                *(uint32_t*)(oh + ((size_t)((b1_ * NH + h) * SEQ + l1_)) * DH + d) =
                    packh2(v1x, v1y);
            } else {
                float* of = (float*)outv;
                *(float2*)(of + (size_t)r0 * 1024 + c) = make_float2(v0x, v0y);
                *(float2*)(of + (size_t)r1 * 1024 + c) = make_float2(v1x, v1y);
            }
        }
    }
}

// ---------------------------------------------------------------------------
// Flash attention (causal), fp16 m16n8k16, P in registers.
// 256 threads (8 warps), q-tile 128 (16 rows/warp), kv-tile 64.
// K/V double-buffered via cp.async (copy of tile jt+1 overlaps compute of jt).
// Q[128][72h] + 2x K[64][72h] + 2x V[64][72h]  (144 B rows, conflict-free LDSM)
// ---------------------------------------------------------------------------
#define ATT_QB 0
#define ATT_KB 18432
#define ATT_VB 36864
#define ATT_SMEM 55296

__device__ __forceinline__ void attn_stage_kv(
    uint32_t sb, const __half* Kg, const __half* Vg, int jt, int tid)
{
    const int buf = jt & 1;
    const uint32_t kb = sb + ATT_KB + buf * 9216;
    const uint32_t vb = sb + ATT_VB + buf * 9216;
    #pragma unroll
    for (int i = 0; i < 2; i++) {
        const int p = tid + i * 256;                 // 0..511
        const int row = p >> 3, c16 = p & 7;
        cpa16(kb + row * 144 + c16 * 16,
              Kg + (size_t)(jt * 64 + row) * 64 + c16 * 8);
        cpa16(vb + row * 144 + c16 * 16,
              Vg + (size_t)(jt * 64 + row) * 64 + c16 * 8);
    }
    CP_COMMIT();
}

__global__ __launch_bounds__(256, 2)
void attn_f16_kernel()
{
    extern __shared__ char smc[];
    const uint32_t sb = smem_u32(smc);

    const int tid  = threadIdx.x;
    const int lane = tid & 31;
    const int wid  = tid >> 5;
    const int g    = lane >> 2;
    const int l4   = lane & 3;
    const int sect = lane >> 3, li = lane & 7;
    const int qt   = gridDim.x - 1 - blockIdx.x;   // heavy blocks first
    const int bh   = blockIdx.y;
    const int m0   = wid * 16;

    const __half* Qg = g_Q + ((size_t)bh * SEQ + qt * 128) * DH;
    const __half* Kg = g_K + (size_t)bh * SEQ * DH;
    const __half* Vg = g_V + (size_t)bh * SEQ * DH;

    const uint32_t qaddr0 = sb + ATT_QB
        + (uint32_t)(m0 + (sect & 1) * 8 + li) * 144 + (sect >> 1) * 16;
    const uint32_t koff = (uint32_t)((sect >> 1) * 8 + li) * 144 + (sect & 1) * 16;
    const uint32_t voff = (uint32_t)((sect & 1) * 8 + li) * 144 + (sect >> 1) * 16;

    // Prologue: stage KV tile 0 (async), then Q (sync stores)
    attn_stage_kv(sb, Kg, Vg, 0, tid);

    const __half2 scl = __half2half2(__float2half(0.125f));
    #pragma unroll
    for (int i = 0; i < 4; i++) {
        const int p = tid + i * 256;
        const int row = p >> 3, dc = (p & 7) * 8;
        uint4 v = *(const uint4*)(Qg + row * 64 + dc);
        __half2* h = (__half2*)&v;
        h[0] = __hmul2(h[0], scl); h[1] = __hmul2(h[1], scl);
        h[2] = __hmul2(h[2], scl); h[3] = __hmul2(h[3], scl);
        *(uint4*)(smc + ATT_QB + row * 144 + dc * 2) = v;
    }
    __syncthreads();

    uint32_t qa[4][4];
    #pragma unroll
    for (int ks = 0; ks < 4; ks++) ldsm4(qa[ks], qaddr0 + ks * 32);

    float o[8][4];
    #pragma unroll
    for (int nt = 0; nt < 8; nt++)
        #pragma unroll
        for (int i = 0; i < 4; i++) o[nt][i] = 0.f;
    float mrow[2] = {-1e30f, -1e30f};
    float lrow[2] = {0.f, 0.f};

    const int R0  = qt * 128 + m0;
    const int r0g = R0 + g;
    const int r1g = r0g + 8;
    const int ntiles = 2 * qt + 2;

    for (int jt = 0; jt < ntiles; jt++) {
        CP_WAIT(0);
        __syncthreads();                       // KV(jt) visible; prev reads done
        if (jt + 1 < ntiles) attn_stage_kv(sb, Kg, Vg, jt + 1, tid);

        if (jt * 64 > R0 + 15) continue;       // warp fully above diagonal

        const int buf = jt & 1;
        const uint32_t kaddr0 = sb + ATT_KB + buf * 9216 + koff;
        const uint32_t vaddr0 = sb + ATT_VB + buf * 9216 + voff;

        // S = Q K^T : 16x64 per warp
        float s[8][4];
        #pragma unroll
        for (int nt = 0; nt < 8; nt++)
            #pragma unroll
            for (int i = 0; i < 4; i++) s[nt][i] = 0.f;

        #pragma unroll
        for (int t = 0; t < 4; t++) {
            #pragma unroll
            for (int ks = 0; ks < 4; ks++) {
                uint32_t kb[4];
                ldsm4(kb, kaddr0 + t * 16 * 144 + ks * 32);
                mma_f16(s[2 * t],     qa[ks][0], qa[ks][1], qa[ks][2], qa[ks][3],
                        kb[0], kb[1]);
                mma_f16(s[2 * t + 1], qa[ks][0], qa[ks][1], qa[ks][2], qa[ks][3],
                        kb[2], kb[3]);
            }
        }

        if (jt * 64 + 63 > R0) {
            #pragma unroll
            for (int nt = 0; nt < 8; nt++) {
                const int c = jt * 64 + nt * 8 + 2 * l4;
                if (c     > r0g) s[nt][0] = -1e30f;
                if (c + 1 > r0g) s[nt][1] = -1e30f;
                if (c     > r1g) s[nt][2] = -1e30f;
                if (c + 1 > r1g) s[nt][3] = -1e30f;
            }
        }

        float mx0 = -1e30f, mx1 = -1e30f;
        #pragma unroll
        for (int nt = 0; nt < 8; nt++) {
            mx0 = fmaxf(mx0, fmaxf(s[nt][0], s[nt][1]));
            mx1 = fmaxf(mx1, fmaxf(s[nt][2], s[nt][3]));
        }
        mx0 = fmaxf(mx0, __shfl_xor_sync(0xffffffffu, mx0, 1));
        mx0 = fmaxf(mx0, __shfl_xor_sync(0xffffffffu, mx0, 2));
        mx1 = fmaxf(mx1, __shfl_xor_sync(0xffffffffu, mx1, 1));
        mx1 = fmaxf(mx1, __shfl_xor_sync(0xffffffffu, mx1, 2));

        const float mn0 = fmaxf(mrow[0], mx0);
        const float mn1 = fmaxf(mrow[1], mx1);
        const float c0 = __expf(mrow[0] - mn0);
        const float c1 = __expf(mrow[1] - mn1);

        float sum0 = 0.f, sum1 = 0.f;
        #pragma unroll
        for (int nt = 0; nt < 8; nt++) {
            s[nt][0] = __expf(s[nt][0] - mn0);
            s[nt][1] = __expf(s[nt][1] - mn0);
            s[nt][2] = __expf(s[nt][2] - mn1);
            s[nt][3] = __expf(s[nt][3] - mn1);
            sum0 += s[nt][0] + s[nt][1];
            sum1 += s[nt][2] + s[nt][3];
        }
        sum0 += __shfl_xor_sync(0xffffffffu, sum0, 1);
        sum0 += __shfl_xor_sync(0xffffffffu, sum0, 2);
        sum1 += __shfl_xor_sync(0xffffffffu, sum1, 1);
        sum1 += __shfl_xor_sync(0xffffffffu, sum1, 2);

        lrow[0] = lrow[0] * c0 + sum0;
        lrow[1] = lrow[1] * c1 + sum1;
        mrow[0] = mn0;
        mrow[1] = mn1;
        #pragma unroll
        for (int nt = 0; nt < 8; nt++) {
            o[nt][0] *= c0; o[nt][1] *= c0;
            o[nt][2] *= c1; o[nt][3] *= c1;
        }

        uint32_t ph[4][4];
        #pragma unroll
        for (int ks = 0; ks < 4; ks++) {
            ph[ks][0] = packh2(s[2 * ks][0],     s[2 * ks][1]);
            ph[ks][1] = packh2(s[2 * ks][2],     s[2 * ks][3]);
            ph[ks][2] = packh2(s[2 * ks + 1][0], s[2 * ks + 1][1]);
            ph[ks][3] = packh2(s[2 * ks + 1][2], s[2 * ks + 1][3]);
        }

        #pragma unroll
        for (int t = 0; t < 4; t++) {
            #pragma unroll
            for (int ks = 0; ks < 4; ks++) {
                uint32_t vb[4];
                ldsm4t(vb, vaddr0 + ks * 16 * 144 + t * 32);
                mma_f16(o[2 * t],     ph[ks][0], ph[ks][1], ph[ks][2], ph[ks][3],
                        vb[0], vb[1]);
                mma_f16(o[2 * t + 1], ph[ks][0], ph[ks][1], ph[ks][2], ph[ks][3],
                        vb[2], vb[3]);
            }
        }
    }

    // Epilogue
    const int b_ = bh >> 4;
    const int h_ = bh & 15;
    const float inv0 = 1.f / lrow[0];
    const float inv1 = 1.f / lrow[1];
    __half* c0p = g_ctx + ((size_t)(b_ * SEQ + qt * 128 + m0 + g))     * DMODEL + h_ * 64;
    __half* c1p = g_ctx + ((size_t)(b_ * SEQ + qt * 128 + m0 + 8 + g)) * DMODEL + h_ * 64;
    #pragma unroll
    for (int nt = 0; nt < 8; nt++) {
        *(uint32_t*)(c0p + nt * 8 + 2 * l4) = packh2(o[nt][0] * inv0, o[nt][1] * inv0);
        *(uint32_t*)(c1p + nt * 8 + 2 * l4) = packh2(o[nt][2] * inv1, o[nt][3] * inv1);
    }
}

// ---------------------------------------------------------------------------
extern "C" void kernel_launch(void* const* d_in, const int* in_sizes, int n_in,
                              void* d_out, int out_size)
{
    const float* x  = (const float*)d_in[0];
    const float* Wq = (const float*)d_in[2];
    const float* bq = (const float*)d_in[3];
    const float* Wk = (const float*)d_in[4];
    const float* bk = (const float*)d_in[5];
    const float* Wv = (const float*)d_in[6];
    const float* bv = (const float*)d_in[7];
    const float* Wo = (const float*)d_in[8];
    const float* bo = (const float*)d_in[9];
    float* out = (float*)d_out;

    __half *xp, *wq, *wk, *wv, *wo, *qp, *kp, *vp, *cp;
    cudaGetSymbolAddress((void**)&xp, g_X);
    cudaGetSymbolAddress((void**)&wq, g_Wq);
    cudaGetSymbolAddress((void**)&wk, g_Wk);
    cudaGetSymbolAddress((void**)&wv, g_Wv);
    cudaGetSymbolAddress((void**)&wo, g_Wo);
    cudaGetSymbolAddress((void**)&qp, g_Q);
    cudaGetSymbolAddress((void**)&kp, g_K);
    cudaGetSymbolAddress((void**)&vp, g_V);
    cudaGetSymbolAddress((void**)&cp, g_ctx);

    // Pre-pass: elementwise fp32 -> fp16 (no transposes)
    const int nx4 = BATCH * SEQ * DMODEL / 4;
    const int nw4 = DMODEL * DMODEL / 4;
    conv_half_kernel<<<(nx4 + 255) / 256, 256>>>((const float4*)x,  (uint2*)xp, nx4);
    conv_half_kernel<<<(nw4 + 255) / 256, 256>>>((const float4*)Wq, (uint2*)wq, nw4);
    conv_half_kernel<<<(nw4 + 255) / 256, 256>>>((const float4*)Wk, (uint2*)wk, nw4);
    conv_half_kernel<<<(nw4 + 255) / 256, 256>>>((const float4*)Wv, (uint2*)wv, nw4);
    conv_half_kernel<<<(nw4 + 255) / 256, 256>>>((const float4*)Wo, (uint2*)wo, nw4);

    cudaFuncSetAttribute(gemm_f16_kernel<true>,
                         cudaFuncAttributeMaxDynamicSharedMemorySize, GEMM_SMEM);
    cudaFuncSetAttribute(gemm_f16_kernel<false>,
                         cudaFuncAttributeMaxDynamicSharedMemorySize, GEMM_SMEM);

    const dim3 ggrid(8, 64);   // N/128, M/128
    gemm_f16_kernel<true><<<ggrid, 256, GEMM_SMEM>>>(xp, wq, bq, qp);
    gemm_f16_kernel<true><<<ggrid, 256, GEMM_SMEM>>>(xp, wk, bk, kp);
    gemm_f16_kernel<true><<<ggrid, 256, GEMM_SMEM>>>(xp, wv, bv, vp);

    cudaFuncSetAttribute(attn_f16_kernel,
                         cudaFuncAttributeMaxDynamicSharedMemorySize, ATT_SMEM);
    attn_f16_kernel<<<dim3(16, 64), 256, ATT_SMEM>>>();

    gemm_f16_kernel<false><<<ggrid, 256, GEMM_SMEM>>>(cp, wo, bo, out);
}